// round 3
// baseline (speedup 1.0000x reference)
#include <cuda_runtime.h>

#define Bb 8
#define Nn 1024
#define Dd 512
#define Hh 8
#define HDIM 64

// Scratch (allocation-free rule: __device__ globals)
__device__ float g_q[Bb*Hh*Nn*HDIM];
__device__ float g_k[Bb*Hh*Nn*HDIM];
__device__ float g_v[Bb*Hh*Nn*HDIM];
__device__ float g_ctx[Bb*Nn*Dd];
__device__ float g_y[Bb*Nn*Dd];

// ---------------------------------------------------------------------------
// QKV projection: C = X @ W^T, written to [B,H,N,HD] layout.
// 128x128x16 tiles, 256 threads, 8x8 register tile per thread.
// ---------------------------------------------------------------------------
__global__ void __launch_bounds__(256) qkv_gemm(
    const float* __restrict__ X,
    const float* __restrict__ Wq,
    const float* __restrict__ Wk,
    const float* __restrict__ Wv)
{
    __shared__ float As[16][132];   // [k][m], padded
    __shared__ float Bs[16][132];   // [k][n], padded

    const int sel = blockIdx.z;
    const float* __restrict__ W = (sel == 0) ? Wq : (sel == 1 ? Wk : Wv);
    float* __restrict__ Out = (sel == 0) ? g_q : (sel == 1 ? g_k : g_v);

    const int m0 = blockIdx.y * 128;
    const int n0 = blockIdx.x * 128;
    const int t  = threadIdx.x;
    const int tx = t & 15;
    const int ty = t >> 4;

    float acc[8][8];
    #pragma unroll
    for (int i = 0; i < 8; i++)
        #pragma unroll
        for (int j = 0; j < 8; j++) acc[i][j] = 0.f;

    for (int k0 = 0; k0 < Dd; k0 += 16) {
        #pragma unroll
        for (int q = 0; q < 2; q++) {
            const int f   = t * 2 + q;       // 0..511
            const int row = f >> 2;          // 0..127
            const int kq  = (f & 3) << 2;    // 0,4,8,12
            float4 av = *(const float4*)&X[(m0 + row) * Dd + k0 + kq];
            As[kq+0][row] = av.x; As[kq+1][row] = av.y;
            As[kq+2][row] = av.z; As[kq+3][row] = av.w;
            float4 bv = *(const float4*)&W[(n0 + row) * Dd + k0 + kq];
            Bs[kq+0][row] = bv.x; Bs[kq+1][row] = bv.y;
            Bs[kq+2][row] = bv.z; Bs[kq+3][row] = bv.w;
        }
        __syncthreads();
        #pragma unroll
        for (int k = 0; k < 16; k++) {
            float a[8], b[8];
            *(float4*)&a[0] = *(const float4*)&As[k][ty * 4];
            *(float4*)&a[4] = *(const float4*)&As[k][64 + ty * 4];
            *(float4*)&b[0] = *(const float4*)&Bs[k][tx * 4];
            *(float4*)&b[4] = *(const float4*)&Bs[k][64 + tx * 4];
            #pragma unroll
            for (int i = 0; i < 8; i++)
                #pragma unroll
                for (int j = 0; j < 8; j++)
                    acc[i][j] = fmaf(a[i], b[j], acc[i][j]);
        }
        __syncthreads();
    }

    // Epilogue: row gm = b*N + n ; col gc = h*64 + hd. Coalesced float4 stores.
    #pragma unroll
    for (int i = 0; i < 8; i++) {
        const int r  = (i < 4) ? (ty * 4 + i) : (64 + ty * 4 + (i - 4));
        const int gm = m0 + r;
        const int bb = gm >> 10;
        const int n  = gm & 1023;
        #pragma unroll
        for (int jh = 0; jh < 2; jh++) {
            const int c  = jh * 64 + tx * 4;
            const int gc = n0 + c;
            const int h  = gc >> 6;
            const int hd = gc & 63;
            float4 o;
            o.x = acc[i][jh*4+0]; o.y = acc[i][jh*4+1];
            o.z = acc[i][jh*4+2]; o.w = acc[i][jh*4+3];
            *(float4*)&Out[(((bb * Hh + h) * Nn) + n) * HDIM + hd] = o;
        }
    }
}

// ---------------------------------------------------------------------------
// Flash attention with adjacency mask. Per block: (b, h, 64-query tile).
// 128 threads. Key tiles of 32. P stays in registers (shfl gather).
// ---------------------------------------------------------------------------
__global__ void __launch_bounds__(128) attn_kernel(const int* __restrict__ adj)
{
    __shared__ float Qs[64][65];
    __shared__ float Ks[32][65];
    __shared__ float Vs[32][64];

    const int qb = blockIdx.x;   // 0..15
    const int h  = blockIdx.y;   // 0..7
    const int b  = blockIdx.z;   // 0..7
    const int t  = threadIdx.x;
    const int tx = t & 7;        // key-group / col-group id (8-lane row group)
    const int ty = t >> 3;       // 0..15
    const int r0 = ty * 4;       // 4 query rows per thread
    const int k0 = tx * 4;       // 4 keys per thread (per 32-key tile)

    const float* __restrict__ Qg = g_q + (((b * Hh + h) * Nn) + qb * 64) * HDIM;
    const float* __restrict__ Kg = g_k + ((b * Hh + h) * Nn) * HDIM;
    const float* __restrict__ Vg = g_v + ((b * Hh + h) * Nn) * HDIM;
    const int*   __restrict__ adjr = adj + (b * Nn + qb * 64) * Nn;

    // Load Q tile 64x64 (1024 float4, 8 per thread)
    #pragma unroll
    for (int it = 0; it < 8; it++) {
        const int i   = t + it * 128;
        const int row = i >> 4;
        const int c4  = (i & 15) << 2;
        float4 v = *(const float4*)&Qg[row * HDIM + c4];
        Qs[row][c4+0] = v.x; Qs[row][c4+1] = v.y;
        Qs[row][c4+2] = v.z; Qs[row][c4+3] = v.w;
    }

    float m[4], l[4], acc[4][8];
    #pragma unroll
    for (int i = 0; i < 4; i++) {
        m[i] = -1e30f; l[i] = 0.f;
        #pragma unroll
        for (int j = 0; j < 8; j++) acc[i][j] = 0.f;
    }

    for (int kt = 0; kt < 32; kt++) {
        __syncthreads();   // Q ready (kt=0) / previous tile consumed
        #pragma unroll
        for (int it = 0; it < 4; it++) {
            const int i   = t + it * 128;
            const int row = i >> 4;
            const int c4  = (i & 15) << 2;
            float4 kv = *(const float4*)&Kg[(kt * 32 + row) * HDIM + c4];
            Ks[row][c4+0] = kv.x; Ks[row][c4+1] = kv.y;
            Ks[row][c4+2] = kv.z; Ks[row][c4+3] = kv.w;
            float4 vv = *(const float4*)&Vg[(kt * 32 + row) * HDIM + c4];
            *(float4*)&Vs[row][c4] = vv;
        }
        __syncthreads();

        // Scores: 4 rows x 4 keys per thread
        float s[4][4];
        #pragma unroll
        for (int i = 0; i < 4; i++)
            #pragma unroll
            for (int j = 0; j < 4; j++) s[i][j] = 0.f;

        #pragma unroll 16
        for (int d = 0; d < HDIM; d++) {
            float qf[4], kf[4];
            #pragma unroll
            for (int i = 0; i < 4; i++) qf[i] = Qs[r0 + i][d];
            #pragma unroll
            for (int j = 0; j < 4; j++) kf[j] = Ks[k0 + j][d];
            #pragma unroll
            for (int i = 0; i < 4; i++)
                #pragma unroll
                for (int j = 0; j < 4; j++)
                    s[i][j] = fmaf(qf[i], kf[j], s[i][j]);
        }

        // Mask + scale (ref: scale first, then masked entries = exactly -10000)
        #pragma unroll
        for (int i = 0; i < 4; i++) {
            const int4 am = *(const int4*)&adjr[(r0 + i) * Nn + kt * 32 + k0];
            s[i][0] = am.x ? s[i][0] * 0.125f : -10000.f;
            s[i][1] = am.y ? s[i][1] * 0.125f : -10000.f;
            s[i][2] = am.z ? s[i][2] * 0.125f : -10000.f;
            s[i][3] = am.w ? s[i][3] * 0.125f : -10000.f;
        }

        // Online softmax per row (8-lane row groups)
        #pragma unroll
        for (int i = 0; i < 4; i++) {
            float mt = fmaxf(fmaxf(s[i][0], s[i][1]), fmaxf(s[i][2], s[i][3]));
            mt = fmaxf(mt, __shfl_xor_sync(0xffffffffu, mt, 1, 8));
            mt = fmaxf(mt, __shfl_xor_sync(0xffffffffu, mt, 2, 8));
            mt = fmaxf(mt, __shfl_xor_sync(0xffffffffu, mt, 4, 8));
            const float nm    = fmaxf(m[i], mt);
            const float alpha = __expf(m[i] - nm);
            m[i] = nm;
            float ps = 0.f;
            #pragma unroll
            for (int j = 0; j < 4; j++) {
                s[i][j] = __expf(s[i][j] - nm);
                ps += s[i][j];
            }
            ps += __shfl_xor_sync(0xffffffffu, ps, 1, 8);
            ps += __shfl_xor_sync(0xffffffffu, ps, 2, 8);
            ps += __shfl_xor_sync(0xffffffffu, ps, 4, 8);
            l[i] = l[i] * alpha + ps;
            #pragma unroll
            for (int j = 0; j < 8; j++) acc[i][j] *= alpha;
        }

        // O += P @ V ; P gathered via shfl within the 8-lane row group
        #pragma unroll
        for (int kk = 0; kk < 32; kk++) {
            const int src = kk >> 2;
            const int jj  = kk & 3;
            const float pv0 = __shfl_sync(0xffffffffu, s[0][jj], src, 8);
            const float pv1 = __shfl_sync(0xffffffffu, s[1][jj], src, 8);
            const float pv2 = __shfl_sync(0xffffffffu, s[2][jj], src, 8);
            const float pv3 = __shfl_sync(0xffffffffu, s[3][jj], src, 8);
            #pragma unroll
            for (int j = 0; j < 8; j++) {
                const float vf = Vs[kk][tx + 8 * j];
                acc[0][j] = fmaf(pv0, vf, acc[0][j]);
                acc[1][j] = fmaf(pv1, vf, acc[1][j]);
                acc[2][j] = fmaf(pv2, vf, acc[2][j]);
                acc[3][j] = fmaf(pv3, vf, acc[3][j]);
            }
        }
    }

    // Write context in [B,N,D] (head-concatenated) layout
    #pragma unroll
    for (int i = 0; i < 4; i++) {
        const float inv = 1.f / l[i];
        const int   n   = qb * 64 + r0 + i;
        float* __restrict__ dst = g_ctx + (b * Nn + n) * Dd + h * HDIM;
        #pragma unroll
        for (int j = 0; j < 8; j++)
            dst[tx + 8 * j] = acc[i][j] * inv;
    }
}

// ---------------------------------------------------------------------------
// Output projection: y = ctx @ Wo^T + bo + x  -> g_y
// ---------------------------------------------------------------------------
__global__ void __launch_bounds__(256) oproj_gemm(
    const float* __restrict__ X,
    const float* __restrict__ Wo,
    const float* __restrict__ bo)
{
    __shared__ float As[16][132];
    __shared__ float Bs[16][132];

    const int m0 = blockIdx.y * 128;
    const int n0 = blockIdx.x * 128;
    const int t  = threadIdx.x;
    const int tx = t & 15;
    const int ty = t >> 4;

    float acc[8][8];
    #pragma unroll
    for (int i = 0; i < 8; i++)
        #pragma unroll
        for (int j = 0; j < 8; j++) acc[i][j] = 0.f;

    for (int k0 = 0; k0 < Dd; k0 += 16) {
        #pragma unroll
        for (int q = 0; q < 2; q++) {
            const int f   = t * 2 + q;
            const int row = f >> 2;
            const int kq  = (f & 3) << 2;
            float4 av = *(const float4*)&g_ctx[(m0 + row) * Dd + k0 + kq];
            As[kq+0][row] = av.x; As[kq+1][row] = av.y;
            As[kq+2][row] = av.z; As[kq+3][row] = av.w;
            float4 bv = *(const float4*)&Wo[(n0 + row) * Dd + k0 + kq];
            Bs[kq+0][row] = bv.x; Bs[kq+1][row] = bv.y;
            Bs[kq+2][row] = bv.z; Bs[kq+3][row] = bv.w;
        }
        __syncthreads();
        #pragma unroll
        for (int k = 0; k < 16; k++) {
            float a[8], b[8];
            *(float4*)&a[0] = *(const float4*)&As[k][ty * 4];
            *(float4*)&a[4] = *(const float4*)&As[k][64 + ty * 4];
            *(float4*)&b[0] = *(const float4*)&Bs[k][tx * 4];
            *(float4*)&b[4] = *(const float4*)&Bs[k][64 + tx * 4];
            #pragma unroll
            for (int i = 0; i < 8; i++)
                #pragma unroll
                for (int j = 0; j < 8; j++)
                    acc[i][j] = fmaf(a[i], b[j], acc[i][j]);
        }
        __syncthreads();
    }

    #pragma unroll
    for (int i = 0; i < 8; i++) {
        const int r  = (i < 4) ? (ty * 4 + i) : (64 + ty * 4 + (i - 4));
        const int gm = m0 + r;
        #pragma unroll
        for (int jh = 0; jh < 2; jh++) {
            const int gc = n0 + jh * 64 + tx * 4;
            float4 xr = *(const float4*)&X[gm * Dd + gc];
            float4 br = *(const float4*)&bo[gc];
            float4 o;
            o.x = acc[i][jh*4+0] + xr.x + br.x;
            o.y = acc[i][jh*4+1] + xr.y + br.y;
            o.z = acc[i][jh*4+2] + xr.z + br.z;
            o.w = acc[i][jh*4+3] + xr.w + br.w;
            *(float4*)&g_y[gm * Dd + gc] = o;
        }
    }
}

// ---------------------------------------------------------------------------
// LayerNorm over D=512 per row
// ---------------------------------------------------------------------------
__global__ void __launch_bounds__(256) ln_kernel(
    const float* __restrict__ gamma,
    const float* __restrict__ beta,
    float* __restrict__ out)
{
    const int row = blockIdx.x;
    const int t   = threadIdx.x;
    const float* __restrict__ y = g_y + row * Dd;

    float2 v = *(const float2*)&y[t * 2];
    float s = v.x + v.y;
    float q = v.x * v.x + v.y * v.y;
    #pragma unroll
    for (int o = 16; o > 0; o >>= 1) {
        s += __shfl_xor_sync(0xffffffffu, s, o);
        q += __shfl_xor_sync(0xffffffffu, q, o);
    }
    __shared__ float ssum[8], ssq[8];
    if ((t & 31) == 0) { ssum[t >> 5] = s; ssq[t >> 5] = q; }
    __syncthreads();
    float ts = 0.f, tq = 0.f;
    #pragma unroll
    for (int w = 0; w < 8; w++) { ts += ssum[w]; tq += ssq[w]; }

    const float mean = ts * (1.f / 512.f);
    const float var  = tq * (1.f / 512.f) - mean * mean;
    const float inv  = rsqrtf(var + 1e-5f);

    float2 g  = *(const float2*)&gamma[t * 2];
    float2 bt = *(const float2*)&beta[t * 2];
    float2 o;
    o.x = (v.x - mean) * inv * g.x + bt.x;
    o.y = (v.y - mean) * inv * g.y + bt.y;
    *(float2*)&out[row * Dd + t * 2] = o;
}

// ---------------------------------------------------------------------------
extern "C" void kernel_launch(void* const* d_in, const int* in_sizes, int n_in,
                              void* d_out, int out_size)
{
    const float* x     = (const float*)d_in[0];
    const int*   adj   = (const int*)  d_in[1];
    const float* wq    = (const float*)d_in[2];
    const float* wk    = (const float*)d_in[3];
    const float* wv    = (const float*)d_in[4];
    const float* wo    = (const float*)d_in[5];
    const float* bo    = (const float*)d_in[6];
    const float* gamma = (const float*)d_in[7];
    const float* beta  = (const float*)d_in[8];
    float* out = (float*)d_out;

    qkv_gemm<<<dim3(Dd / 128, (Bb * Nn) / 128, 3), 256>>>(x, wq, wk, wv);
    attn_kernel<<<dim3(Nn / 64, Hh, Bb), 128>>>(adj);
    oproj_gemm<<<dim3(Dd / 128, (Bb * Nn) / 128, 1), 256>>>(x, wo, bo);
    ln_kernel<<<Bb * Nn, 256>>>(gamma, beta, out);
}

// round 4
// speedup vs baseline: 2.0954x; 2.0954x over previous
#include <cuda_runtime.h>
#include <cuda_bf16.h>

#define Bb 8
#define Nn 1024
#define Dd 512
#define Hh 8
#define HDIM 64

typedef __nv_bfloat16 bf16;

// ---------------- device scratch (allocation-free rule) ----------------
__device__ __align__(256) bf16 g_xhi[Bb*Nn*Dd], g_xlo[Bb*Nn*Dd];
__device__ __align__(256) bf16 g_whi[4*Dd*Dd], g_wlo[4*Dd*Dd];      // wq,wk,wv,wo
__device__ __align__(256) bf16 g_qhi[Bb*Hh*Nn*HDIM], g_qlo[Bb*Hh*Nn*HDIM];
__device__ __align__(256) bf16 g_khi[Bb*Hh*Nn*HDIM], g_klo[Bb*Hh*Nn*HDIM];
__device__ __align__(256) bf16 g_vthi[Bb*Hh*HDIM*Nn], g_vtlo[Bb*Hh*HDIM*Nn]; // [B,H,hd,N]
__device__ __align__(256) bf16 g_chi[Bb*Nn*Dd], g_clo[Bb*Nn*Dd];    // attention context
__device__ __align__(256) float g_y[Bb*Nn*Dd];
__device__ __align__(256) unsigned g_adjbits[Bb*Nn*Nn/32];

// ---------------- helpers ----------------
__device__ __forceinline__ unsigned pack2(__nv_bfloat16 a, __nv_bfloat16 b) {
    __nv_bfloat162 t = __halves2bfloat162(a, b);
    return *(unsigned*)&t;
}
__device__ __forceinline__ void split2(float a, float b, unsigned& hi, unsigned& lo) {
    __nv_bfloat16 ah = __float2bfloat16(a), bh = __float2bfloat16(b);
    __nv_bfloat16 al = __float2bfloat16(a - __bfloat162float(ah));
    __nv_bfloat16 bl = __float2bfloat16(b - __bfloat162float(bh));
    hi = pack2(ah, bh); lo = pack2(al, bl);
}
__device__ __forceinline__ unsigned lds_u32(const bf16* p, int elem) {
    return *(const unsigned*)(p + elem);
}
__device__ __forceinline__ void mma_bf16(float& c0, float& c1, float& c2, float& c3,
                                         unsigned a0, unsigned a1, unsigned a2, unsigned a3,
                                         unsigned b0, unsigned b1) {
    asm volatile(
        "mma.sync.aligned.m16n8k16.row.col.f32.bf16.bf16.f32 "
        "{%0,%1,%2,%3},{%4,%5,%6,%7},{%8,%9},{%0,%1,%2,%3};\n"
        : "+f"(c0), "+f"(c1), "+f"(c2), "+f"(c3)
        : "r"(a0), "r"(a1), "r"(a2), "r"(a3), "r"(b0), "r"(b1));
}

// ---------------- fp32 -> bf16 hi/lo split ----------------
__global__ void __launch_bounds__(256) split_kernel(const float* __restrict__ src, int which) {
    const int n = (which == 0) ? (Bb*Nn*Dd) : (Dd*Dd);
    const int i = (blockIdx.x * 256 + threadIdx.x) * 4;
    if (i >= n) return;
    bf16 *hi, *lo;
    if (which == 0) { hi = g_xhi; lo = g_xlo; }
    else            { hi = g_whi + (which - 1) * Dd * Dd; lo = g_wlo + (which - 1) * Dd * Dd; }
    float4 v = *(const float4*)(src + i);
    unsigned h0, l0, h1, l1;
    split2(v.x, v.y, h0, l0);
    split2(v.z, v.w, h1, l1);
    uint2 ho; ho.x = h0; ho.y = h1;
    uint2 lw; lw.x = l0; lw.y = l1;
    *(uint2*)&hi[i] = ho;
    *(uint2*)&lo[i] = lw;
}

// ---------------- adj -> bitmask ----------------
__global__ void __launch_bounds__(256) pack_adj_kernel(const int* __restrict__ adj) {
    const int idx = blockIdx.x * 256 + threadIdx.x;   // < B*N*N/32
    const int4* p = (const int4*)(adj + idx * 32);
    unsigned w = 0;
    #pragma unroll
    for (int j = 0; j < 8; j++) {
        int4 a = p[j];
        w |= (a.x != 0 ? 1u : 0u) << (j * 4 + 0);
        w |= (a.y != 0 ? 1u : 0u) << (j * 4 + 1);
        w |= (a.z != 0 ? 1u : 0u) << (j * 4 + 2);
        w |= (a.w != 0 ? 1u : 0u) << (j * 4 + 3);
    }
    g_adjbits[idx] = w;
}

// ---------------- bf16-split GEMM: C[128x64] = A[128xK] @ B[NxK]^T ----------------
// modes: 0=Q out, 1=K out, 2=V out (transposed layout), 3=O-proj (+x+bo -> g_y fp32)
// mode_p < 0 -> mode = blockIdx.z (qkv launch)
#define GLDA 40   // 32 + 8 pad (bf16 elems)
__global__ void __launch_bounds__(256) gemm_bf16(int mode_p,
                                                 const float* __restrict__ xres,
                                                 const float* __restrict__ bo) {
    __shared__ __align__(16) char smraw[35840];
    bf16* sAh = (bf16*)(smraw);          // 128 x 40
    bf16* sAl = (bf16*)(smraw + 10240);
    bf16* sBh = (bf16*)(smraw + 20480);  // 64 x 40
    bf16* sBl = (bf16*)(smraw + 25600);

    const int mode = (mode_p < 0) ? blockIdx.z : mode_p;
    const bf16* __restrict__ Ahi = (mode == 3) ? g_chi : g_xhi;
    const bf16* __restrict__ Alo = (mode == 3) ? g_clo : g_xlo;
    const bf16* __restrict__ Bhi = g_whi + mode * Dd * Dd;
    const bf16* __restrict__ Blo = g_wlo + mode * Dd * Dd;

    const int m0 = blockIdx.y * 128;
    const int n0 = blockIdx.x * 64;
    const int t  = threadIdx.x;
    const int l  = t & 31;
    const int wid = t >> 5;
    const int wm = wid >> 1;   // 0..3
    const int wn = wid & 1;    // 0..1

    float acc[2][4][4];
    #pragma unroll
    for (int mi = 0; mi < 2; mi++)
        #pragma unroll
        for (int ni = 0; ni < 4; ni++)
            #pragma unroll
            for (int c = 0; c < 4; c++) acc[mi][ni][c] = 0.f;

    for (int k0 = 0; k0 < Dd; k0 += 32) {
        __syncthreads();
        // load A tile 128x32 (hi,lo)
        #pragma unroll
        for (int it = 0; it < 2; it++) {
            const int u = t + it * 256;
            const int row = u >> 2;
            const int c8 = (u & 3) * 8;
            *(uint4*)&sAh[row * GLDA + c8] = *(const uint4*)&Ahi[(m0 + row) * Dd + k0 + c8];
            *(uint4*)&sAl[row * GLDA + c8] = *(const uint4*)&Alo[(m0 + row) * Dd + k0 + c8];
        }
        // load B tile 64x32 (hi,lo)
        {
            const int row = t >> 2;
            const int c8 = (t & 3) * 8;
            *(uint4*)&sBh[row * GLDA + c8] = *(const uint4*)&Bhi[(n0 + row) * Dd + k0 + c8];
            *(uint4*)&sBl[row * GLDA + c8] = *(const uint4*)&Blo[(n0 + row) * Dd + k0 + c8];
        }
        __syncthreads();

        #pragma unroll
        for (int ks = 0; ks < 2; ks++) {
            const int kc = ks * 16 + (l & 3) * 2;
            unsigned ah[2][4], al[2][4];
            #pragma unroll
            for (int mi = 0; mi < 2; mi++) {
                const int rb = wm * 32 + mi * 16 + (l >> 2);
                ah[mi][0] = lds_u32(sAh, rb * GLDA + kc);
                ah[mi][1] = lds_u32(sAh, (rb + 8) * GLDA + kc);
                ah[mi][2] = lds_u32(sAh, rb * GLDA + kc + 8);
                ah[mi][3] = lds_u32(sAh, (rb + 8) * GLDA + kc + 8);
                al[mi][0] = lds_u32(sAl, rb * GLDA + kc);
                al[mi][1] = lds_u32(sAl, (rb + 8) * GLDA + kc);
                al[mi][2] = lds_u32(sAl, rb * GLDA + kc + 8);
                al[mi][3] = lds_u32(sAl, (rb + 8) * GLDA + kc + 8);
            }
            #pragma unroll
            for (int ni = 0; ni < 4; ni++) {
                const int nb = wn * 32 + ni * 8 + (l >> 2);
                unsigned bh0 = lds_u32(sBh, nb * GLDA + kc);
                unsigned bh1 = lds_u32(sBh, nb * GLDA + kc + 8);
                unsigned bl0 = lds_u32(sBl, nb * GLDA + kc);
                unsigned bl1 = lds_u32(sBl, nb * GLDA + kc + 8);
                #pragma unroll
                for (int mi = 0; mi < 2; mi++) {
                    float* c = acc[mi][ni];
                    mma_bf16(c[0], c[1], c[2], c[3], ah[mi][0], ah[mi][1], ah[mi][2], ah[mi][3], bh0, bh1);
                    mma_bf16(c[0], c[1], c[2], c[3], ah[mi][0], ah[mi][1], ah[mi][2], ah[mi][3], bl0, bl1);
                    mma_bf16(c[0], c[1], c[2], c[3], al[mi][0], al[mi][1], al[mi][2], al[mi][3], bh0, bh1);
                }
            }
        }
    }

    // -------- epilogue --------
    if (mode == 0 || mode == 1) {
        bf16* oh = (mode == 0) ? g_qhi : g_khi;
        bf16* ol = (mode == 0) ? g_qlo : g_klo;
        const int h = blockIdx.x;
        #pragma unroll
        for (int mi = 0; mi < 2; mi++)
            #pragma unroll
            for (int ni = 0; ni < 4; ni++) {
                const int m  = m0 + wm * 32 + mi * 16 + (l >> 2);
                const int hd = wn * 32 + ni * 8 + (l & 3) * 2;
                const float* c = acc[mi][ni];
                #pragma unroll
                for (int rr = 0; rr < 2; rr++) {
                    const int mr = m + rr * 8;
                    const int b  = mr >> 10;
                    const int n  = mr & 1023;
                    const int idx = (((b * Hh + h) * Nn) + n) * HDIM + hd;
                    unsigned hu, lu;
                    split2(c[rr * 2 + 0], c[rr * 2 + 1], hu, lu);
                    *(unsigned*)&oh[idx] = hu;
                    *(unsigned*)&ol[idx] = lu;
                }
            }
    } else if (mode == 2) {
        // bounce through smem, emit transposed [B,H,hd,N]
        __syncthreads();
        float* sf = (float*)smraw;   // 128 x 68
        #pragma unroll
        for (int mi = 0; mi < 2; mi++)
            #pragma unroll
            for (int ni = 0; ni < 4; ni++) {
                const int mb = wm * 32 + mi * 16 + (l >> 2);
                const int cc = wn * 32 + ni * 8 + (l & 3) * 2;
                const float* c = acc[mi][ni];
                float2 v0; v0.x = c[0]; v0.y = c[1];
                float2 v1; v1.x = c[2]; v1.y = c[3];
                *(float2*)&sf[mb * 68 + cc]       = v0;
                *(float2*)&sf[(mb + 8) * 68 + cc] = v1;
            }
        __syncthreads();
        const int h = blockIdx.x;
        const int b = m0 >> 10;
        const int ntok0 = m0 & 1023;
        const int hd = t & 63;
        const int tg = t >> 6;          // 0..3  (32 tokens each)
        unsigned hbuf[16], lbuf[16];
        #pragma unroll
        for (int j = 0; j < 32; j += 2) {
            float v0 = sf[(tg * 32 + j) * 68 + hd];
            float v1 = sf[(tg * 32 + j + 1) * 68 + hd];
            split2(v0, v1, hbuf[j >> 1], lbuf[j >> 1]);
        }
        const int base = (((b * Hh + h) * HDIM) + hd) * Nn + ntok0 + tg * 32;
        #pragma unroll
        for (int q = 0; q < 4; q++) {
            *(uint4*)&g_vthi[base + q * 8] = *(uint4*)&hbuf[q * 4];
            *(uint4*)&g_vtlo[base + q * 8] = *(uint4*)&lbuf[q * 4];
        }
    } else {
        // oproj: y = acc + x + bo  -> g_y (fp32)
        #pragma unroll
        for (int mi = 0; mi < 2; mi++)
            #pragma unroll
            for (int ni = 0; ni < 4; ni++) {
                const int m  = m0 + wm * 32 + mi * 16 + (l >> 2);
                const int gc = n0 + wn * 32 + ni * 8 + (l & 3) * 2;
                const float* c = acc[mi][ni];
                float2 bv = *(const float2*)&bo[gc];
                #pragma unroll
                for (int rr = 0; rr < 2; rr++) {
                    const int mr = m + rr * 8;
                    float2 xv = *(const float2*)&xres[mr * Dd + gc];
                    float2 o;
                    o.x = c[rr * 2 + 0] + xv.x + bv.x;
                    o.y = c[rr * 2 + 1] + xv.y + bv.y;
                    *(float2*)&g_y[mr * Dd + gc] = o;
                }
            }
    }
}

// ---------------- flash attention, bf16-split mma ----------------
#define ALD 72   // 64 + 8 pad
__global__ void __launch_bounds__(128) attn_kernel() {
    extern __shared__ bf16 sm_att[];
    bf16* sQh = sm_att;              // 64 x 72
    bf16* sQl = sm_att + 4608;
    bf16* sKh = sm_att + 9216;
    bf16* sKl = sm_att + 13824;
    bf16* sVh = sm_att + 18432;      // VT: [hd][key]
    bf16* sVl = sm_att + 23040;

    const int qt = blockIdx.x;       // 0..15
    const int h  = blockIdx.y;
    const int b  = blockIdx.z;
    const int bh = b * Hh + h;
    const int t  = threadIdx.x;
    const int l  = t & 31;
    const int w  = t >> 5;           // warp: 16 q rows each

    // load Q tile 64x64 (hi,lo)
    #pragma unroll
    for (int it = 0; it < 4; it++) {
        const int u = t + it * 128;
        const int row = u >> 3;
        const int c8 = (u & 7) * 8;
        *(uint4*)&sQh[row * ALD + c8] = *(const uint4*)&g_qhi[((bh * Nn) + qt * 64 + row) * HDIM + c8];
        *(uint4*)&sQl[row * ALD + c8] = *(const uint4*)&g_qlo[((bh * Nn) + qt * 64 + row) * HDIM + c8];
    }

    float o[8][4];
    #pragma unroll
    for (int nj = 0; nj < 8; nj++)
        #pragma unroll
        for (int c = 0; c < 4; c++) o[nj][c] = 0.f;
    float m0s = -1e30f, m1s = -1e30f, l0s = 0.f, l1s = 0.f;

    const int qg0 = qt * 64 + w * 16 + (l >> 2);   // row0 (row1 = +8)

    for (int kt = 0; kt < 16; kt++) {
        __syncthreads();
        #pragma unroll
        for (int it = 0; it < 4; it++) {
            const int u = t + it * 128;
            const int row = u >> 3;
            const int c8 = (u & 7) * 8;
            *(uint4*)&sKh[row * ALD + c8] = *(const uint4*)&g_khi[((bh * Nn) + kt * 64 + row) * HDIM + c8];
            *(uint4*)&sKl[row * ALD + c8] = *(const uint4*)&g_klo[((bh * Nn) + kt * 64 + row) * HDIM + c8];
            *(uint4*)&sVh[row * ALD + c8] = *(const uint4*)&g_vthi[((bh * HDIM) + row) * Nn + kt * 64 + c8];
            *(uint4*)&sVl[row * ALD + c8] = *(const uint4*)&g_vtlo[((bh * HDIM) + row) * Nn + kt * 64 + c8];
        }
        __syncthreads();

        // ---- scores S[16 x 64] per warp ----
        float s[8][4];
        #pragma unroll
        for (int ni = 0; ni < 8; ni++)
            #pragma unroll
            for (int c = 0; c < 4; c++) s[ni][c] = 0.f;

        #pragma unroll
        for (int kd = 0; kd < 4; kd++) {
            const int kc = kd * 16 + (l & 3) * 2;
            const int rb = w * 16 + (l >> 2);
            unsigned qh[4], ql[4];
            qh[0] = lds_u32(sQh, rb * ALD + kc);
            qh[1] = lds_u32(sQh, (rb + 8) * ALD + kc);
            qh[2] = lds_u32(sQh, rb * ALD + kc + 8);
            qh[3] = lds_u32(sQh, (rb + 8) * ALD + kc + 8);
            ql[0] = lds_u32(sQl, rb * ALD + kc);
            ql[1] = lds_u32(sQl, (rb + 8) * ALD + kc);
            ql[2] = lds_u32(sQl, rb * ALD + kc + 8);
            ql[3] = lds_u32(sQl, (rb + 8) * ALD + kc + 8);
            #pragma unroll
            for (int ni = 0; ni < 8; ni++) {
                const int nb = ni * 8 + (l >> 2);
                unsigned bh0 = lds_u32(sKh, nb * ALD + kc);
                unsigned bh1 = lds_u32(sKh, nb * ALD + kc + 8);
                unsigned bl0 = lds_u32(sKl, nb * ALD + kc);
                unsigned bl1 = lds_u32(sKl, nb * ALD + kc + 8);
                float* c = s[ni];
                mma_bf16(c[0], c[1], c[2], c[3], qh[0], qh[1], qh[2], qh[3], bh0, bh1);
                mma_bf16(c[0], c[1], c[2], c[3], qh[0], qh[1], qh[2], qh[3], bl0, bl1);
                mma_bf16(c[0], c[1], c[2], c[3], ql[0], ql[1], ql[2], ql[3], bh0, bh1);
            }
        }

        // ---- mask + scale ----
        const unsigned* mp0 = g_adjbits + (b * Nn + qg0) * (Nn / 32) + kt * 2;
        const unsigned* mp1 = g_adjbits + (b * Nn + qg0 + 8) * (Nn / 32) + kt * 2;
        uint2 mw0 = *(const uint2*)mp0;
        uint2 mw1 = *(const uint2*)mp1;
        #pragma unroll
        for (int ni = 0; ni < 8; ni++) {
            const int k0 = ni * 8 + (l & 3) * 2;
            const unsigned b0 = (((k0 < 32) ? mw0.x : mw0.y) >> (k0 & 31)) & 3u;
            const unsigned b1 = (((k0 < 32) ? mw1.x : mw1.y) >> (k0 & 31)) & 3u;
            s[ni][0] = (b0 & 1u) ? s[ni][0] * 0.125f : -10000.f;
            s[ni][1] = (b0 & 2u) ? s[ni][1] * 0.125f : -10000.f;
            s[ni][2] = (b1 & 1u) ? s[ni][2] * 0.125f : -10000.f;
            s[ni][3] = (b1 & 2u) ? s[ni][3] * 0.125f : -10000.f;
        }

        // ---- online softmax ----
        float mx0 = -1e30f, mx1 = -1e30f;
        #pragma unroll
        for (int ni = 0; ni < 8; ni++) {
            mx0 = fmaxf(mx0, fmaxf(s[ni][0], s[ni][1]));
            mx1 = fmaxf(mx1, fmaxf(s[ni][2], s[ni][3]));
        }
        mx0 = fmaxf(mx0, __shfl_xor_sync(0xffffffffu, mx0, 1));
        mx0 = fmaxf(mx0, __shfl_xor_sync(0xffffffffu, mx0, 2));
        mx1 = fmaxf(mx1, __shfl_xor_sync(0xffffffffu, mx1, 1));
        mx1 = fmaxf(mx1, __shfl_xor_sync(0xffffffffu, mx1, 2));
        const float nm0 = fmaxf(m0s, mx0);
        const float nm1 = fmaxf(m1s, mx1);
        const float al0 = __expf(m0s - nm0);
        const float al1 = __expf(m1s - nm1);
        m0s = nm0; m1s = nm1;
        #pragma unroll
        for (int nj = 0; nj < 8; nj++) {
            o[nj][0] *= al0; o[nj][1] *= al0;
            o[nj][2] *= al1; o[nj][3] *= al1;
        }

        // ---- p = exp(s - m), pack to bf16 hi/lo A-frags, PV mma ----
        float sum0 = 0.f, sum1 = 0.f;
        #pragma unroll
        for (int ks = 0; ks < 4; ks++) {
            unsigned pa[4], pl[4];
            #pragma unroll
            for (int q = 0; q < 2; q++) {
                const int ni = 2 * ks + q;
                float p0 = __expf(s[ni][0] - nm0);
                float p1 = __expf(s[ni][1] - nm0);
                float p2 = __expf(s[ni][2] - nm1);
                float p3 = __expf(s[ni][3] - nm1);
                sum0 += p0 + p1; sum1 += p2 + p3;
                split2(p0, p1, pa[q * 2 + 0], pl[q * 2 + 0]);   // row0 regs (a0 / a2)
                split2(p2, p3, pa[q * 2 + 1], pl[q * 2 + 1]);   // row1 regs (a1 / a3)
            }
            const int kc = ks * 16 + (l & 3) * 2;
            #pragma unroll
            for (int nj = 0; nj < 8; nj++) {
                const int nb = nj * 8 + (l >> 2);
                unsigned bh0 = lds_u32(sVh, nb * ALD + kc);
                unsigned bh1 = lds_u32(sVh, nb * ALD + kc + 8);
                unsigned bl0 = lds_u32(sVl, nb * ALD + kc);
                unsigned bl1 = lds_u32(sVl, nb * ALD + kc + 8);
                float* c = o[nj];
                mma_bf16(c[0], c[1], c[2], c[3], pa[0], pa[1], pa[2], pa[3], bh0, bh1);
                mma_bf16(c[0], c[1], c[2], c[3], pa[0], pa[1], pa[2], pa[3], bl0, bl1);
                mma_bf16(c[0], c[1], c[2], c[3], pl[0], pl[1], pl[2], pl[3], bh0, bh1);
            }
        }
        sum0 += __shfl_xor_sync(0xffffffffu, sum0, 1);
        sum0 += __shfl_xor_sync(0xffffffffu, sum0, 2);
        sum1 += __shfl_xor_sync(0xffffffffu, sum1, 1);
        sum1 += __shfl_xor_sync(0xffffffffu, sum1, 2);
        l0s = l0s * al0 + sum0;
        l1s = l1s * al1 + sum1;
    }

    // ---- epilogue: ctx (bf16 hi/lo, [B,N,D] head-concat) ----
    const float inv0 = 1.f / l0s;
    const float inv1 = 1.f / l1s;
    const int row0g = b * Nn + qg0;
    #pragma unroll
    for (int nj = 0; nj < 8; nj++) {
        const int c = h * HDIM + nj * 8 + (l & 3) * 2;
        unsigned hu, lu;
        split2(o[nj][0] * inv0, o[nj][1] * inv0, hu, lu);
        *(unsigned*)&g_chi[row0g * Dd + c] = hu;
        *(unsigned*)&g_clo[row0g * Dd + c] = lu;
        split2(o[nj][2] * inv1, o[nj][3] * inv1, hu, lu);
        *(unsigned*)&g_chi[(row0g + 8) * Dd + c] = hu;
        *(unsigned*)&g_clo[(row0g + 8) * Dd + c] = lu;
    }
}

// ---------------- LayerNorm over D=512 per row ----------------
__global__ void __launch_bounds__(256) ln_kernel(
    const float* __restrict__ gamma,
    const float* __restrict__ beta,
    float* __restrict__ out)
{
    const int row = blockIdx.x;
    const int t   = threadIdx.x;
    const float* __restrict__ y = g_y + row * Dd;

    float2 v = *(const float2*)&y[t * 2];
    float s = v.x + v.y;
    float q = v.x * v.x + v.y * v.y;
    #pragma unroll
    for (int o = 16; o > 0; o >>= 1) {
        s += __shfl_xor_sync(0xffffffffu, s, o);
        q += __shfl_xor_sync(0xffffffffu, q, o);
    }
    __shared__ float ssum[8], ssq[8];
    if ((t & 31) == 0) { ssum[t >> 5] = s; ssq[t >> 5] = q; }
    __syncthreads();
    float ts = 0.f, tq = 0.f;
    #pragma unroll
    for (int wv = 0; wv < 8; wv++) { ts += ssum[wv]; tq += ssq[wv]; }

    const float mean = ts * (1.f / 512.f);
    const float var  = tq * (1.f / 512.f) - mean * mean;
    const float inv  = rsqrtf(var + 1e-5f);

    float2 g  = *(const float2*)&gamma[t * 2];
    float2 bt = *(const float2*)&beta[t * 2];
    float2 o;
    o.x = (v.x - mean) * inv * g.x + bt.x;
    o.y = (v.y - mean) * inv * g.y + bt.y;
    *(float2*)&out[row * Dd + t * 2] = o;
}

// ---------------------------------------------------------------------------
extern "C" void kernel_launch(void* const* d_in, const int* in_sizes, int n_in,
                              void* d_out, int out_size)
{
    const float* x     = (const float*)d_in[0];
    const int*   adj   = (const int*)  d_in[1];
    const float* wq    = (const float*)d_in[2];
    const float* wk    = (const float*)d_in[3];
    const float* wv    = (const float*)d_in[4];
    const float* wo    = (const float*)d_in[5];
    const float* bo    = (const float*)d_in[6];
    const float* gamma = (const float*)d_in[7];
    const float* beta  = (const float*)d_in[8];
    float* out = (float*)d_out;

    cudaFuncSetAttribute(attn_kernel, cudaFuncAttributeMaxDynamicSharedMemorySize, 55296);

    split_kernel<<<4096, 256>>>(x, 0);
    split_kernel<<<256, 256>>>(wq, 1);
    split_kernel<<<256, 256>>>(wk, 2);
    split_kernel<<<256, 256>>>(wv, 3);
    split_kernel<<<256, 256>>>(wo, 4);
    pack_adj_kernel<<<1024, 256>>>(adj);

    gemm_bf16<<<dim3(8, 64, 3), 256>>>(-1, nullptr, nullptr);
    attn_kernel<<<dim3(16, 8, 8), 128, 55296>>>();
    gemm_bf16<<<dim3(8, 64, 1), 256>>>(3, x, bo);
    ln_kernel<<<Bb * Nn, 256>>>(gamma, beta, out);
}

// round 5
// speedup vs baseline: 2.1142x; 1.0090x over previous
#include <cuda_runtime.h>
#include <cuda_bf16.h>

#define Bb 8
#define Nn 1024
#define Dd 512
#define Hh 8
#define HDIM 64

typedef __nv_bfloat16 bf16;

// ---------------- device scratch (allocation-free rule) ----------------
__device__ __align__(256) bf16 g_xhi[Bb*Nn*Dd], g_xlo[Bb*Nn*Dd];
__device__ __align__(256) bf16 g_whi[4*Dd*Dd], g_wlo[4*Dd*Dd];      // wq,wk,wv,wo
__device__ __align__(256) bf16 g_qhi[Bb*Hh*Nn*HDIM], g_qlo[Bb*Hh*Nn*HDIM];
__device__ __align__(256) bf16 g_khi[Bb*Hh*Nn*HDIM], g_klo[Bb*Hh*Nn*HDIM];
__device__ __align__(256) bf16 g_vthi[Bb*Hh*HDIM*Nn], g_vtlo[Bb*Hh*HDIM*Nn]; // [B,H,hd,N]
__device__ __align__(256) bf16 g_chi[Bb*Nn*Dd], g_clo[Bb*Nn*Dd];    // attention context
__device__ __align__(256) float g_y[Bb*Nn*Dd];
__device__ __align__(256) unsigned g_adjbits[Bb*Nn*Nn/32];

// ---------------- helpers ----------------
__device__ __forceinline__ unsigned pack2(__nv_bfloat16 a, __nv_bfloat16 b) {
    __nv_bfloat162 t = __halves2bfloat162(a, b);
    return *(unsigned*)&t;
}
__device__ __forceinline__ void split2(float a, float b, unsigned& hi, unsigned& lo) {
    __nv_bfloat16 ah = __float2bfloat16(a), bh = __float2bfloat16(b);
    __nv_bfloat16 al = __float2bfloat16(a - __bfloat162float(ah));
    __nv_bfloat16 bl = __float2bfloat16(b - __bfloat162float(bh));
    hi = pack2(ah, bh); lo = pack2(al, bl);
}
__device__ __forceinline__ unsigned lds_u32(const bf16* p, int elem) {
    return *(const unsigned*)(p + elem);
}
__device__ __forceinline__ void mma_bf16(float& c0, float& c1, float& c2, float& c3,
                                         unsigned a0, unsigned a1, unsigned a2, unsigned a3,
                                         unsigned b0, unsigned b1) {
    asm volatile(
        "mma.sync.aligned.m16n8k16.row.col.f32.bf16.bf16.f32 "
        "{%0,%1,%2,%3},{%4,%5,%6,%7},{%8,%9},{%0,%1,%2,%3};\n"
        : "+f"(c0), "+f"(c1), "+f"(c2), "+f"(c3)
        : "r"(a0), "r"(a1), "r"(a2), "r"(a3), "r"(b0), "r"(b1));
}
__device__ __forceinline__ void cp16(void* dst_smem, const void* src) {
    unsigned d = (unsigned)__cvta_generic_to_shared(dst_smem);
    asm volatile("cp.async.cg.shared.global [%0], [%1], 16;\n" :: "r"(d), "l"(src));
}
__device__ __forceinline__ void cp_commit() { asm volatile("cp.async.commit_group;\n" ::); }
__device__ __forceinline__ void cp_wait1()  { asm volatile("cp.async.wait_group 1;\n" ::); }
__device__ __forceinline__ void cp_wait0()  { asm volatile("cp.async.wait_group 0;\n" ::); }

// ---------------- fused prologue: fp32->bf16 hi/lo splits + adj bitmask ----------------
__global__ void __launch_bounds__(256) prep_kernel(
    const float* __restrict__ x,
    const float* __restrict__ wq, const float* __restrict__ wk,
    const float* __restrict__ wv, const float* __restrict__ wo,
    const int* __restrict__ adj)
{
    const int blk = blockIdx.x;
    const int t   = threadIdx.x;
    if (blk < 4096) {                       // x split: 8192*512 floats
        const int i = (blk * 256 + t) * 4;
        float4 v = *(const float4*)(x + i);
        unsigned h0, l0, h1, l1;
        split2(v.x, v.y, h0, l0);
        split2(v.z, v.w, h1, l1);
        uint2 ho; ho.x = h0; ho.y = h1;
        uint2 lw; lw.x = l0; lw.y = l1;
        *(uint2*)&g_xhi[i] = ho;
        *(uint2*)&g_xlo[i] = lw;
    } else if (blk < 5120) {                // 4 weight splits: 512*512 floats each
        const int wsel = (blk - 4096) >> 8;
        const float* src = (wsel == 0) ? wq : (wsel == 1) ? wk : (wsel == 2) ? wv : wo;
        const int i = (((blk - 4096) & 255) * 256 + t) * 4;
        float4 v = *(const float4*)(src + i);
        unsigned h0, l0, h1, l1;
        split2(v.x, v.y, h0, l0);
        split2(v.z, v.w, h1, l1);
        uint2 ho; ho.x = h0; ho.y = h1;
        uint2 lw; lw.x = l0; lw.y = l1;
        *(uint2*)&g_whi[wsel * Dd * Dd + i] = ho;
        *(uint2*)&g_wlo[wsel * Dd * Dd + i] = lw;
    } else {                                // adj pack: 262144 words
        const int idx = (blk - 5120) * 256 + t;
        const int4* p = (const int4*)(adj + idx * 32);
        unsigned wbits = 0;
        #pragma unroll
        for (int j = 0; j < 8; j++) {
            int4 a = p[j];
            wbits |= (a.x != 0 ? 1u : 0u) << (j * 4 + 0);
            wbits |= (a.y != 0 ? 1u : 0u) << (j * 4 + 1);
            wbits |= (a.z != 0 ? 1u : 0u) << (j * 4 + 2);
            wbits |= (a.w != 0 ? 1u : 0u) << (j * 4 + 3);
        }
        g_adjbits[idx] = wbits;
    }
}

// ---------------- bf16-split GEMM: C[128x64] = A[128xK] @ B[NxK]^T ----------------
// modes: 0=Q out, 1=K out, 2=V out (transposed layout), 3=O-proj (+x+bo -> g_y fp32)
// mode_p < 0 -> mode = blockIdx.z (qkv launch). Double-buffered cp.async pipeline.
#define GLDA 40             // 32 + 8 pad (bf16 elems)
#define GSTAGE 30720        // bytes per stage: 2*10240 (A) + 2*5120 (B)
__global__ void __launch_bounds__(256) gemm_bf16(int mode_p,
                                                 const float* __restrict__ xres,
                                                 const float* __restrict__ bo) {
    extern __shared__ __align__(16) char smraw[];

    const int mode = (mode_p < 0) ? blockIdx.z : mode_p;
    const bf16* __restrict__ Ahi = (mode == 3) ? g_chi : g_xhi;
    const bf16* __restrict__ Alo = (mode == 3) ? g_clo : g_xlo;
    const bf16* __restrict__ Bhi = g_whi + mode * Dd * Dd;
    const bf16* __restrict__ Blo = g_wlo + mode * Dd * Dd;

    const int m0 = blockIdx.y * 128;
    const int n0 = blockIdx.x * 64;
    const int t  = threadIdx.x;
    const int l  = t & 31;
    const int wid = t >> 5;
    const int wm = wid >> 1;   // 0..3
    const int wn = wid & 1;    // 0..1

    float acc[2][4][4];
    #pragma unroll
    for (int mi = 0; mi < 2; mi++)
        #pragma unroll
        for (int ni = 0; ni < 4; ni++)
            #pragma unroll
            for (int c = 0; c < 4; c++) acc[mi][ni][c] = 0.f;

    // stage loader
    auto load_stage = [&](int s, int k0) {
        char* base = smraw + s * GSTAGE;
        bf16* pAh = (bf16*)base;
        bf16* pAl = (bf16*)(base + 10240);
        bf16* pBh = (bf16*)(base + 20480);
        bf16* pBl = (bf16*)(base + 25600);
        #pragma unroll
        for (int it = 0; it < 2; it++) {
            const int u   = t + it * 256;
            const int row = u >> 2;
            const int c8  = (u & 3) * 8;
            cp16(&pAh[row * GLDA + c8], &Ahi[(m0 + row) * Dd + k0 + c8]);
            cp16(&pAl[row * GLDA + c8], &Alo[(m0 + row) * Dd + k0 + c8]);
        }
        {
            const int row = t >> 2;
            const int c8  = (t & 3) * 8;
            cp16(&pBh[row * GLDA + c8], &Bhi[(n0 + row) * Dd + k0 + c8]);
            cp16(&pBl[row * GLDA + c8], &Blo[(n0 + row) * Dd + k0 + c8]);
        }
    };

    load_stage(0, 0);
    cp_commit();

    for (int ki = 0; ki < 16; ki++) {
        if (ki < 15) { load_stage((ki + 1) & 1, (ki + 1) * 32); cp_commit(); cp_wait1(); }
        else         { cp_wait0(); }
        __syncthreads();

        char* base = smraw + (ki & 1) * GSTAGE;
        bf16* sAh = (bf16*)base;
        bf16* sAl = (bf16*)(base + 10240);
        bf16* sBh = (bf16*)(base + 20480);
        bf16* sBl = (bf16*)(base + 25600);

        #pragma unroll
        for (int ks = 0; ks < 2; ks++) {
            const int kc = ks * 16 + (l & 3) * 2;
            unsigned ah[2][4], al[2][4];
            #pragma unroll
            for (int mi = 0; mi < 2; mi++) {
                const int rb = wm * 32 + mi * 16 + (l >> 2);
                ah[mi][0] = lds_u32(sAh, rb * GLDA + kc);
                ah[mi][1] = lds_u32(sAh, (rb + 8) * GLDA + kc);
                ah[mi][2] = lds_u32(sAh, rb * GLDA + kc + 8);
                ah[mi][3] = lds_u32(sAh, (rb + 8) * GLDA + kc + 8);
                al[mi][0] = lds_u32(sAl, rb * GLDA + kc);
                al[mi][1] = lds_u32(sAl, (rb + 8) * GLDA + kc);
                al[mi][2] = lds_u32(sAl, rb * GLDA + kc + 8);
                al[mi][3] = lds_u32(sAl, (rb + 8) * GLDA + kc + 8);
            }
            #pragma unroll
            for (int ni = 0; ni < 4; ni++) {
                const int nb = wn * 32 + ni * 8 + (l >> 2);
                unsigned bh0 = lds_u32(sBh, nb * GLDA + kc);
                unsigned bh1 = lds_u32(sBh, nb * GLDA + kc + 8);
                unsigned bl0 = lds_u32(sBl, nb * GLDA + kc);
                unsigned bl1 = lds_u32(sBl, nb * GLDA + kc + 8);
                #pragma unroll
                for (int mi = 0; mi < 2; mi++) {
                    float* c = acc[mi][ni];
                    mma_bf16(c[0], c[1], c[2], c[3], ah[mi][0], ah[mi][1], ah[mi][2], ah[mi][3], bh0, bh1);
                    mma_bf16(c[0], c[1], c[2], c[3], ah[mi][0], ah[mi][1], ah[mi][2], ah[mi][3], bl0, bl1);
                    mma_bf16(c[0], c[1], c[2], c[3], al[mi][0], al[mi][1], al[mi][2], al[mi][3], bh0, bh1);
                }
            }
        }
        __syncthreads();
    }

    // -------- epilogue --------
    if (mode == 0 || mode == 1) {
        bf16* oh = (mode == 0) ? g_qhi : g_khi;
        bf16* ol = (mode == 0) ? g_qlo : g_klo;
        const int h = blockIdx.x;
        #pragma unroll
        for (int mi = 0; mi < 2; mi++)
            #pragma unroll
            for (int ni = 0; ni < 4; ni++) {
                const int m  = m0 + wm * 32 + mi * 16 + (l >> 2);
                const int hd = wn * 32 + ni * 8 + (l & 3) * 2;
                const float* c = acc[mi][ni];
                #pragma unroll
                for (int rr = 0; rr < 2; rr++) {
                    const int mr = m + rr * 8;
                    const int b  = mr >> 10;
                    const int n  = mr & 1023;
                    const int idx = (((b * Hh + h) * Nn) + n) * HDIM + hd;
                    unsigned hu, lu;
                    split2(c[rr * 2 + 0], c[rr * 2 + 1], hu, lu);
                    *(unsigned*)&oh[idx] = hu;
                    *(unsigned*)&ol[idx] = lu;
                }
            }
    } else if (mode == 2) {
        // bounce through smem, emit transposed [B,H,hd,N]
        __syncthreads();
        float* sf = (float*)smraw;   // 128 x 68
        #pragma unroll
        for (int mi = 0; mi < 2; mi++)
            #pragma unroll
            for (int ni = 0; ni < 4; ni++) {
                const int mb = wm * 32 + mi * 16 + (l >> 2);
                const int cc = wn * 32 + ni * 8 + (l & 3) * 2;
                const float* c = acc[mi][ni];
                float2 v0; v0.x = c[0]; v0.y = c[1];
                float2 v1; v1.x = c[2]; v1.y = c[3];
                *(float2*)&sf[mb * 68 + cc]       = v0;
                *(float2*)&sf[(mb + 8) * 68 + cc] = v1;
            }
        __syncthreads();
        const int h = blockIdx.x;
        const int b = m0 >> 10;
        const int ntok0 = m0 & 1023;
        const int hd = t & 63;
        const int tg = t >> 6;          // 0..3  (32 tokens each)
        unsigned hbuf[16], lbuf[16];
        #pragma unroll
        for (int j = 0; j < 32; j += 2) {
            float v0 = sf[(tg * 32 + j) * 68 + hd];
            float v1 = sf[(tg * 32 + j + 1) * 68 + hd];
            split2(v0, v1, hbuf[j >> 1], lbuf[j >> 1]);
        }
        const int base = (((b * Hh + h) * HDIM) + hd) * Nn + ntok0 + tg * 32;
        #pragma unroll
        for (int q = 0; q < 4; q++) {
            *(uint4*)&g_vthi[base + q * 8] = *(uint4*)&hbuf[q * 4];
            *(uint4*)&g_vtlo[base + q * 8] = *(uint4*)&lbuf[q * 4];
        }
    } else {
        // oproj: y = acc + x + bo  -> g_y (fp32)
        #pragma unroll
        for (int mi = 0; mi < 2; mi++)
            #pragma unroll
            for (int ni = 0; ni < 4; ni++) {
                const int m  = m0 + wm * 32 + mi * 16 + (l >> 2);
                const int gc = n0 + wn * 32 + ni * 8 + (l & 3) * 2;
                const float* c = acc[mi][ni];
                float2 bv = *(const float2*)&bo[gc];
                #pragma unroll
                for (int rr = 0; rr < 2; rr++) {
                    const int mr = m + rr * 8;
                    float2 xv = *(const float2*)&xres[mr * Dd + gc];
                    float2 o;
                    o.x = c[rr * 2 + 0] + xv.x + bv.x;
                    o.y = c[rr * 2 + 1] + xv.y + bv.y;
                    *(float2*)&g_y[mr * Dd + gc] = o;
                }
            }
    }
}

// ---------------- flash attention, bf16-split mma, cp.async double buffer ----------------
// 256 threads, 8 warps x 16 query rows = 128-row Q tile. Q frags in registers.
#define ALD 72              // 64 + 8 pad (bf16 elems)
#define ASTAGE 18432        // elems per stage: 4 arrays x 64x72
__global__ void __launch_bounds__(256) attn_kernel() {
    extern __shared__ bf16 smatt[];

    const int qt = blockIdx.x;       // 0..7 (128-row Q tiles)
    const int h  = blockIdx.y;
    const int b  = blockIdx.z;
    const int bh = b * Hh + h;
    const int t  = threadIdx.x;
    const int l  = t & 31;
    const int w  = t >> 5;           // warp 0..7: 16 q rows each
    const int rq = qt * 128 + w * 16 + (l >> 2);   // global q row0 (row1 = +8)

    // ---- Q fragments: loop-invariant, straight from gmem into registers ----
    unsigned qfh[4][4], qfl[4][4];
    {
        const bf16* Q0h = g_qhi + (bh * Nn + rq) * HDIM;
        const bf16* Q0l = g_qlo + (bh * Nn + rq) * HDIM;
        #pragma unroll
        for (int kd = 0; kd < 4; kd++) {
            const int kc = kd * 16 + (l & 3) * 2;
            qfh[kd][0] = *(const unsigned*)&Q0h[kc];
            qfh[kd][1] = *(const unsigned*)&Q0h[8 * HDIM + kc];
            qfh[kd][2] = *(const unsigned*)&Q0h[kc + 8];
            qfh[kd][3] = *(const unsigned*)&Q0h[8 * HDIM + kc + 8];
            qfl[kd][0] = *(const unsigned*)&Q0l[kc];
            qfl[kd][1] = *(const unsigned*)&Q0l[8 * HDIM + kc];
            qfl[kd][2] = *(const unsigned*)&Q0l[kc + 8];
            qfl[kd][3] = *(const unsigned*)&Q0l[8 * HDIM + kc + 8];
        }
    }

    float o[8][4];
    #pragma unroll
    for (int nj = 0; nj < 8; nj++)
        #pragma unroll
        for (int c = 0; c < 4; c++) o[nj][c] = 0.f;
    float m0s = -1e30f, m1s = -1e30f, l0s = 0.f, l1s = 0.f;

    auto load_stage = [&](int s, int kt) {
        bf16* base = smatt + s * ASTAGE;
        bf16* pKh = base;
        bf16* pKl = base + 4608;
        bf16* pVh = base + 9216;
        bf16* pVl = base + 13824;
        #pragma unroll
        for (int it = 0; it < 2; it++) {
            const int u   = t + it * 256;
            const int row = u >> 3;
            const int c8  = (u & 7) * 8;
            cp16(&pKh[row * ALD + c8], &g_khi[((bh * Nn) + kt * 64 + row) * HDIM + c8]);
            cp16(&pKl[row * ALD + c8], &g_klo[((bh * Nn) + kt * 64 + row) * HDIM + c8]);
            cp16(&pVh[row * ALD + c8], &g_vthi[((bh * HDIM) + row) * Nn + kt * 64 + c8]);
            cp16(&pVl[row * ALD + c8], &g_vtlo[((bh * HDIM) + row) * Nn + kt * 64 + c8]);
        }
    };

    load_stage(0, 0);
    cp_commit();

    for (int kt = 0; kt < 16; kt++) {
        if (kt < 15) { load_stage((kt + 1) & 1, kt + 1); cp_commit(); cp_wait1(); }
        else         { cp_wait0(); }
        __syncthreads();

        bf16* base = smatt + (kt & 1) * ASTAGE;
        bf16* sKh = base;
        bf16* sKl = base + 4608;
        bf16* sVh = base + 9216;
        bf16* sVl = base + 13824;

        // ---- scores S[16 x 64] per warp ----
        float s[8][4];
        #pragma unroll
        for (int ni = 0; ni < 8; ni++)
            #pragma unroll
            for (int c = 0; c < 4; c++) s[ni][c] = 0.f;

        #pragma unroll
        for (int kd = 0; kd < 4; kd++) {
            const int kc = kd * 16 + (l & 3) * 2;
            #pragma unroll
            for (int ni = 0; ni < 8; ni++) {
                const int nb = ni * 8 + (l >> 2);
                unsigned bh0 = lds_u32(sKh, nb * ALD + kc);
                unsigned bh1 = lds_u32(sKh, nb * ALD + kc + 8);
                unsigned bl0 = lds_u32(sKl, nb * ALD + kc);
                unsigned bl1 = lds_u32(sKl, nb * ALD + kc + 8);
                float* c = s[ni];
                mma_bf16(c[0], c[1], c[2], c[3], qfh[kd][0], qfh[kd][1], qfh[kd][2], qfh[kd][3], bh0, bh1);
                mma_bf16(c[0], c[1], c[2], c[3], qfh[kd][0], qfh[kd][1], qfh[kd][2], qfh[kd][3], bl0, bl1);
                mma_bf16(c[0], c[1], c[2], c[3], qfl[kd][0], qfl[kd][1], qfl[kd][2], qfl[kd][3], bh0, bh1);
            }
        }

        // ---- mask + scale (scale first; masked -> exactly -10000) ----
        const unsigned* mp0 = g_adjbits + (b * Nn + rq) * (Nn / 32) + kt * 2;
        const unsigned* mp1 = g_adjbits + (b * Nn + rq + 8) * (Nn / 32) + kt * 2;
        uint2 mw0 = *(const uint2*)mp0;
        uint2 mw1 = *(const uint2*)mp1;
        #pragma unroll
        for (int ni = 0; ni < 8; ni++) {
            const int k0 = ni * 8 + (l & 3) * 2;
            const unsigned b0 = (((k0 < 32) ? mw0.x : mw0.y) >> (k0 & 31)) & 3u;
            const unsigned b1 = (((k0 < 32) ? mw1.x : mw1.y) >> (k0 & 31)) & 3u;
            s[ni][0] = (b0 & 1u) ? s[ni][0] * 0.125f : -10000.f;
            s[ni][1] = (b0 & 2u) ? s[ni][1] * 0.125f : -10000.f;
            s[ni][2] = (b1 & 1u) ? s[ni][2] * 0.125f : -10000.f;
            s[ni][3] = (b1 & 2u) ? s[ni][3] * 0.125f : -10000.f;
        }

        // ---- online softmax (quad reduction over the 4 lanes of each row) ----
        float mx0 = -1e30f, mx1 = -1e30f;
        #pragma unroll
        for (int ni = 0; ni < 8; ni++) {
            mx0 = fmaxf(mx0, fmaxf(s[ni][0], s[ni][1]));
            mx1 = fmaxf(mx1, fmaxf(s[ni][2], s[ni][3]));
        }
        mx0 = fmaxf(mx0, __shfl_xor_sync(0xffffffffu, mx0, 1));
        mx0 = fmaxf(mx0, __shfl_xor_sync(0xffffffffu, mx0, 2));
        mx1 = fmaxf(mx1, __shfl_xor_sync(0xffffffffu, mx1, 1));
        mx1 = fmaxf(mx1, __shfl_xor_sync(0xffffffffu, mx1, 2));
        const float nm0 = fmaxf(m0s, mx0);
        const float nm1 = fmaxf(m1s, mx1);
        const float al0 = __expf(m0s - nm0);
        const float al1 = __expf(m1s - nm1);
        m0s = nm0; m1s = nm1;
        #pragma unroll
        for (int nj = 0; nj < 8; nj++) {
            o[nj][0] *= al0; o[nj][1] *= al0;
            o[nj][2] *= al1; o[nj][3] *= al1;
        }

        // ---- p = exp(s - m), pack to bf16 hi/lo A-frags in registers, PV mma ----
        float sum0 = 0.f, sum1 = 0.f;
        #pragma unroll
        for (int ks = 0; ks < 4; ks++) {
            unsigned pa[4], pl[4];
            #pragma unroll
            for (int q = 0; q < 2; q++) {
                const int ni = 2 * ks + q;
                float p0 = __expf(s[ni][0] - nm0);
                float p1 = __expf(s[ni][1] - nm0);
                float p2 = __expf(s[ni][2] - nm1);
                float p3 = __expf(s[ni][3] - nm1);
                sum0 += p0 + p1; sum1 += p2 + p3;
                split2(p0, p1, pa[q * 2 + 0], pl[q * 2 + 0]);   // row0 regs (a0 / a2)
                split2(p2, p3, pa[q * 2 + 1], pl[q * 2 + 1]);   // row1 regs (a1 / a3)
            }
            const int kc = ks * 16 + (l & 3) * 2;
            #pragma unroll
            for (int nj = 0; nj < 8; nj++) {
                const int nb = nj * 8 + (l >> 2);
                unsigned bh0 = lds_u32(sVh, nb * ALD + kc);
                unsigned bh1 = lds_u32(sVh, nb * ALD + kc + 8);
                unsigned bl0 = lds_u32(sVl, nb * ALD + kc);
                unsigned bl1 = lds_u32(sVl, nb * ALD + kc + 8);
                float* c = o[nj];
                mma_bf16(c[0], c[1], c[2], c[3], pa[0], pa[1], pa[2], pa[3], bh0, bh1);
                mma_bf16(c[0], c[1], c[2], c[3], pa[0], pa[1], pa[2], pa[3], bl0, bl1);
                mma_bf16(c[0], c[1], c[2], c[3], pl[0], pl[1], pl[2], pl[3], bh0, bh1);
            }
        }
        sum0 += __shfl_xor_sync(0xffffffffu, sum0, 1);
        sum0 += __shfl_xor_sync(0xffffffffu, sum0, 2);
        sum1 += __shfl_xor_sync(0xffffffffu, sum1, 1);
        sum1 += __shfl_xor_sync(0xffffffffu, sum1, 2);
        l0s = l0s * al0 + sum0;
        l1s = l1s * al1 + sum1;

        __syncthreads();   // all warps done with this stage before it's reloaded
    }

    // ---- epilogue: ctx (bf16 hi/lo, [B,N,D] head-concat) ----
    const float inv0 = 1.f / l0s;
    const float inv1 = 1.f / l1s;
    const int row0g = b * Nn + rq;
    #pragma unroll
    for (int nj = 0; nj < 8; nj++) {
        const int c = h * HDIM + nj * 8 + (l & 3) * 2;
        unsigned hu, lu;
        split2(o[nj][0] * inv0, o[nj][1] * inv0, hu, lu);
        *(unsigned*)&g_chi[row0g * Dd + c] = hu;
        *(unsigned*)&g_clo[row0g * Dd + c] = lu;
        split2(o[nj][2] * inv1, o[nj][3] * inv1, hu, lu);
        *(unsigned*)&g_chi[(row0g + 8) * Dd + c] = hu;
        *(unsigned*)&g_clo[(row0g + 8) * Dd + c] = lu;
    }
}

// ---------------- LayerNorm over D=512 per row ----------------
__global__ void __launch_bounds__(256) ln_kernel(
    const float* __restrict__ gamma,
    const float* __restrict__ beta,
    float* __restrict__ out)
{
    const int row = blockIdx.x;
    const int t   = threadIdx.x;
    const float* __restrict__ y = g_y + row * Dd;

    float2 v = *(const float2*)&y[t * 2];
    float s = v.x + v.y;
    float q = v.x * v.x + v.y * v.y;
    #pragma unroll
    for (int o = 16; o > 0; o >>= 1) {
        s += __shfl_xor_sync(0xffffffffu, s, o);
        q += __shfl_xor_sync(0xffffffffu, q, o);
    }
    __shared__ float ssum[8], ssq[8];
    if ((t & 31) == 0) { ssum[t >> 5] = s; ssq[t >> 5] = q; }
    __syncthreads();
    float ts = 0.f, tq = 0.f;
    #pragma unroll
    for (int wv = 0; wv < 8; wv++) { ts += ssum[wv]; tq += ssq[wv]; }

    const float mean = ts * (1.f / 512.f);
    const float var  = tq * (1.f / 512.f) - mean * mean;
    const float inv  = rsqrtf(var + 1e-5f);

    float2 g  = *(const float2*)&gamma[t * 2];
    float2 bt = *(const float2*)&beta[t * 2];
    float2 o;
    o.x = (v.x - mean) * inv * g.x + bt.x;
    o.y = (v.y - mean) * inv * g.y + bt.y;
    *(float2*)&out[row * Dd + t * 2] = o;
}

// ---------------------------------------------------------------------------
extern "C" void kernel_launch(void* const* d_in, const int* in_sizes, int n_in,
                              void* d_out, int out_size)
{
    const float* x     = (const float*)d_in[0];
    const int*   adj   = (const int*)  d_in[1];
    const float* wq    = (const float*)d_in[2];
    const float* wk    = (const float*)d_in[3];
    const float* wv    = (const float*)d_in[4];
    const float* wo    = (const float*)d_in[5];
    const float* bo    = (const float*)d_in[6];
    const float* gamma = (const float*)d_in[7];
    const float* beta  = (const float*)d_in[8];
    float* out = (float*)d_out;

    static bool attr_done = false;
    if (!attr_done) {
        cudaFuncSetAttribute(attn_kernel, cudaFuncAttributeMaxDynamicSharedMemorySize, 2 * ASTAGE * 2);
        cudaFuncSetAttribute(gemm_bf16,  cudaFuncAttributeMaxDynamicSharedMemorySize, 2 * GSTAGE);
        attr_done = true;
    }

    prep_kernel<<<6144, 256>>>(x, wq, wk, wv, wo, adj);
    gemm_bf16<<<dim3(8, 64, 3), 256, 2 * GSTAGE>>>(-1, nullptr, nullptr);
    attn_kernel<<<dim3(8, 8, 8), 256, 2 * ASTAGE * 2>>>();
    gemm_bf16<<<dim3(8, 64, 1), 256, 2 * GSTAGE>>>(3, x, bo);
    ln_kernel<<<Bb * Nn, 256>>>(gamma, beta, out);
}

// round 6
// speedup vs baseline: 2.9741x; 1.4067x over previous
#include <cuda_runtime.h>

#define Bb 8
#define Nn 1024
#define Dd 512
#define Hh 8
#define HDIM 64

// ---------------- device scratch (allocation-free rule) ----------------
__device__ __align__(256) float g_q [Bb*Hh*Nn*HDIM];
__device__ __align__(256) float g_k [Bb*Hh*Nn*HDIM];
__device__ __align__(256) float g_vt[Bb*Hh*HDIM*Nn];   // [B,H,hd,N]
__device__ __align__(256) float g_c [Bb*Nn*Dd];        // attention context
__device__ __align__(256) float g_y [Bb*Nn*Dd];
__device__ __align__(256) unsigned g_adjbits[Bb*Nn*Nn/32];

// ---------------- helpers ----------------
// tf32 mma, k-dim mapping: physical k pair (2t,2t+1) fed as mma-k (t, t+4) on BOTH
// operands -> dot product order-permuted but exact. Lets every fragment be one LDS.64.
__device__ __forceinline__ void mma_tf32(float& c0, float& c1, float& c2, float& c3,
                                         unsigned a0, unsigned a1, unsigned a2, unsigned a3,
                                         unsigned b0, unsigned b1) {
    asm volatile(
        "mma.sync.aligned.m16n8k8.row.col.f32.tf32.tf32.f32 "
        "{%0,%1,%2,%3},{%4,%5,%6,%7},{%8,%9},{%0,%1,%2,%3};\n"
        : "+f"(c0), "+f"(c1), "+f"(c2), "+f"(c3)
        : "r"(a0), "r"(a1), "r"(a2), "r"(a3), "r"(b0), "r"(b1));
}
__device__ __forceinline__ void cp16(void* dst_smem, const void* src) {
    unsigned d = (unsigned)__cvta_generic_to_shared(dst_smem);
    asm volatile("cp.async.cg.shared.global [%0], [%1], 16;\n" :: "r"(d), "l"(src));
}
__device__ __forceinline__ void cp_commit() { asm volatile("cp.async.commit_group;\n" ::); }
__device__ __forceinline__ void cp_wait1()  { asm volatile("cp.async.wait_group 1;\n" ::); }
__device__ __forceinline__ void cp_wait0()  { asm volatile("cp.async.wait_group 0;\n" ::); }

// ---------------- prologue: adj -> bitmask ----------------
__global__ void __launch_bounds__(256) prep_kernel(const int* __restrict__ adj) {
    const int idx = blockIdx.x * 256 + threadIdx.x;   // < B*N*N/32
    const int4* p = (const int4*)(adj + idx * 32);
    unsigned w = 0;
    #pragma unroll
    for (int j = 0; j < 8; j++) {
        int4 a = p[j];
        w |= (a.x != 0 ? 1u : 0u) << (j * 4 + 0);
        w |= (a.y != 0 ? 1u : 0u) << (j * 4 + 1);
        w |= (a.z != 0 ? 1u : 0u) << (j * 4 + 2);
        w |= (a.w != 0 ? 1u : 0u) << (j * 4 + 3);
    }
    g_adjbits[idx] = w;
}

// ---------------- tf32 GEMM: C[128x64] = A[128xK] @ W[NxK]^T ----------------
// modes: 0=Q out, 1=K out, 2=V out (transposed [B,H,hd,N]), 3=O-proj (+x+bo -> g_y)
#define GST 40                       // A/B smem row stride (words); 40 == 8 mod 32 -> conflict-free LDS.64
#define GSTAGEF (128*GST + 64*GST)   // floats per stage = 7680 (30720 B)
__global__ void __launch_bounds__(256, 3) gemm_tf32(int mode_p,
    const float* __restrict__ Ax,
    const float* __restrict__ W0, const float* __restrict__ W1, const float* __restrict__ W2,
    const float* __restrict__ xres, const float* __restrict__ bo)
{
    extern __shared__ float smg[];

    const int mode = (mode_p < 0) ? blockIdx.z : mode_p;
    const float* __restrict__ A = (mode == 3) ? g_c : Ax;
    const float* __restrict__ W = (mode_p < 0)
        ? (blockIdx.z == 0 ? W0 : (blockIdx.z == 1 ? W1 : W2)) : W0;

    const int m0 = blockIdx.y * 128;
    const int n0 = blockIdx.x * 64;
    const int t  = threadIdx.x;
    const int l  = t & 31;
    const int wid = t >> 5;
    const int wm = wid >> 1;   // 0..3
    const int wn = wid & 1;    // 0..1

    float acc[2][4][4];
    #pragma unroll
    for (int mi = 0; mi < 2; mi++)
        #pragma unroll
        for (int ni = 0; ni < 4; ni++)
            #pragma unroll
            for (int c = 0; c < 4; c++) acc[mi][ni][c] = 0.f;

    auto load_stage = [&](int s, int k0) {
        float* sA = smg + s * GSTAGEF;
        float* sB = sA + 128 * GST;
        #pragma unroll
        for (int it = 0; it < 4; it++) {
            const int u = t + it * 256;
            const int row = u >> 3;
            const int ch  = (u & 7) * 4;
            cp16(&sA[row * GST + ch], &A[(m0 + row) * Dd + k0 + ch]);
        }
        #pragma unroll
        for (int it = 0; it < 2; it++) {
            const int u = t + it * 256;
            const int row = u >> 3;
            const int ch  = (u & 7) * 4;
            cp16(&sB[row * GST + ch], &W[(n0 + row) * Dd + k0 + ch]);
        }
    };

    load_stage(0, 0);
    cp_commit();

    for (int ki = 0; ki < 16; ki++) {
        if (ki < 15) { load_stage((ki + 1) & 1, (ki + 1) * 32); cp_commit(); cp_wait1(); }
        else         { cp_wait0(); }
        __syncthreads();

        const float* sA = smg + (ki & 1) * GSTAGEF;
        const float* sB = sA + 128 * GST;

        #pragma unroll
        for (int ks = 0; ks < 4; ks++) {
            const int kc = ks * 8 + 2 * (l & 3);
            unsigned af[2][4];
            #pragma unroll
            for (int mi = 0; mi < 2; mi++) {
                const int rb = wm * 32 + mi * 16 + (l >> 2);
                uint2 a01 = *(const uint2*)(sA + rb * GST + kc);
                uint2 a23 = *(const uint2*)(sA + (rb + 8) * GST + kc);
                af[mi][0] = a01.x; af[mi][1] = a23.x; af[mi][2] = a01.y; af[mi][3] = a23.y;
            }
            #pragma unroll
            for (int ni = 0; ni < 4; ni++) {
                const int nb = wn * 32 + ni * 8 + (l >> 2);
                uint2 bv = *(const uint2*)(sB + nb * GST + kc);
                #pragma unroll
                for (int mi = 0; mi < 2; mi++) {
                    float* c = acc[mi][ni];
                    mma_tf32(c[0], c[1], c[2], c[3],
                             af[mi][0], af[mi][1], af[mi][2], af[mi][3], bv.x, bv.y);
                }
            }
        }
        __syncthreads();
    }

    // -------- epilogue --------
    if (mode == 0 || mode == 1) {
        float* O = (mode == 0) ? g_q : g_k;
        const int h = blockIdx.x;
        #pragma unroll
        for (int mi = 0; mi < 2; mi++)
            #pragma unroll
            for (int ni = 0; ni < 4; ni++) {
                const int m  = m0 + wm * 32 + mi * 16 + (l >> 2);
                const int hd = wn * 32 + ni * 8 + 2 * (l & 3);
                const float* c = acc[mi][ni];
                #pragma unroll
                for (int rr = 0; rr < 2; rr++) {
                    const int mr = m + rr * 8;
                    const int b  = mr >> 10;
                    const int n  = mr & 1023;
                    float2 v; v.x = c[rr * 2 + 0]; v.y = c[rr * 2 + 1];
                    *(float2*)&O[(((b * Hh + h) * Nn) + n) * HDIM + hd] = v;
                }
            }
    } else if (mode == 2) {
        // bounce through smem (stride 72 -> conflict-free), emit transposed [B,H,hd,N]
        __syncthreads();
        float* sf = smg;   // 128 x 72 floats = 9216 <= 15360
        #pragma unroll
        for (int mi = 0; mi < 2; mi++)
            #pragma unroll
            for (int ni = 0; ni < 4; ni++) {
                const int mb = wm * 32 + mi * 16 + (l >> 2);
                const int cc = wn * 32 + ni * 8 + 2 * (l & 3);
                const float* c = acc[mi][ni];
                float2 v0; v0.x = c[0]; v0.y = c[1];
                float2 v1; v1.x = c[2]; v1.y = c[3];
                *(float2*)(sf + mb * 72 + cc)       = v0;
                *(float2*)(sf + (mb + 8) * 72 + cc) = v1;
            }
        __syncthreads();
        const int h = blockIdx.x;
        const int b = m0 >> 10;
        const int ntok0 = m0 & 1023;
        const int hd = t & 63;
        const int tg = t >> 6;          // 0..3 (32 tokens each)
        const int gbase = (((b * Hh + h) * HDIM) + hd) * Nn + ntok0 + tg * 32;
        #pragma unroll
        for (int j4 = 0; j4 < 8; j4++) {
            float4 v;
            v.x = sf[(tg * 32 + j4 * 4 + 0) * 72 + hd];
            v.y = sf[(tg * 32 + j4 * 4 + 1) * 72 + hd];
            v.z = sf[(tg * 32 + j4 * 4 + 2) * 72 + hd];
            v.w = sf[(tg * 32 + j4 * 4 + 3) * 72 + hd];
            *(float4*)&g_vt[gbase + j4 * 4] = v;
        }
    } else {
        // oproj: y = acc + x + bo  -> g_y (fp32)
        #pragma unroll
        for (int mi = 0; mi < 2; mi++)
            #pragma unroll
            for (int ni = 0; ni < 4; ni++) {
                const int m  = m0 + wm * 32 + mi * 16 + (l >> 2);
                const int gc = n0 + wn * 32 + ni * 8 + 2 * (l & 3);
                const float* c = acc[mi][ni];
                float2 bv = *(const float2*)&bo[gc];
                #pragma unroll
                for (int rr = 0; rr < 2; rr++) {
                    const int mr = m + rr * 8;
                    float2 xv = *(const float2*)&xres[mr * Dd + gc];
                    float2 o;
                    o.x = c[rr * 2 + 0] + xv.x + bv.x;
                    o.y = c[rr * 2 + 1] + xv.y + bv.y;
                    *(float2*)&g_y[mr * Dd + gc] = o;
                }
            }
    }
}

// ---------------- flash attention, tf32 mma ----------------
// 256 threads, 8 warps x 16 q rows = 128-row Q tile; K-tile = 32 keys, double-buffered.
// Q in smem (stride 72), K [key][hd] stride 72, V^T [hd][key] stride 40 -> all LDS.64 conflict-free.
// P(C-frag) -> PV A-frag is a pure register reorder (p0,p2,p1,p3).
#define QS 72
#define KS 72
#define VS 40
#define ASTAGEF (32*KS + 64*VS)      // 4864 floats per stage
#define AQF (128*QS)                 // 9216 floats
__global__ void __launch_bounds__(256, 3) attn_kernel() {
    extern __shared__ float sma[];
    float* sQ = sma;                         // 128 x 72

    const int qt = blockIdx.x;   // 0..7
    const int h  = blockIdx.y;
    const int b  = blockIdx.z;
    const int bh = b * Hh + h;
    const int t  = threadIdx.x;
    const int l  = t & 31;
    const int w  = t >> 5;                   // 16 q rows per warp
    const int rq = qt * 128 + w * 16 + (l >> 2);   // q row0 (row1 = +8)

    // Q tile -> smem (async, part of group 0)
    #pragma unroll
    for (int it = 0; it < 8; it++) {
        const int u = t + it * 256;
        const int row = u >> 4;
        const int ch  = (u & 15) * 4;
        cp16(&sQ[row * QS + ch], &g_q[((bh * Nn) + qt * 128 + row) * HDIM + ch]);
    }

    auto load_stage = [&](int s, int kt) {
        float* sK = sma + AQF + s * ASTAGEF;
        float* sV = sK + 32 * KS;
        #pragma unroll
        for (int it = 0; it < 2; it++) {
            const int u = t + it * 256;
            { const int row = u >> 4, ch = (u & 15) * 4;
              cp16(&sK[row * KS + ch], &g_k[((bh * Nn) + kt * 32 + row) * HDIM + ch]); }
            { const int row = u >> 3, ch = (u & 7) * 4;
              cp16(&sV[row * VS + ch], &g_vt[((bh * HDIM) + row) * Nn + kt * 32 + ch]); }
        }
    };

    load_stage(0, 0);
    cp_commit();

    float o[8][4];
    #pragma unroll
    for (int nj = 0; nj < 8; nj++)
        #pragma unroll
        for (int c = 0; c < 4; c++) o[nj][c] = 0.f;
    float m0s = -1e30f, m1s = -1e30f, l0s = 0.f, l1s = 0.f;

    for (int kt = 0; kt < 32; kt++) {
        if (kt < 31) { load_stage((kt + 1) & 1, kt + 1); cp_commit(); cp_wait1(); }
        else         { cp_wait0(); }
        __syncthreads();

        const float* sK = sma + AQF + (kt & 1) * ASTAGEF;
        const float* sV = sK + 32 * KS;

        // ---- scores S[16 x 32] per warp ----
        float s[4][4];
        #pragma unroll
        for (int ni = 0; ni < 4; ni++)
            #pragma unroll
            for (int c = 0; c < 4; c++) s[ni][c] = 0.f;

        #pragma unroll
        for (int kd = 0; kd < 8; kd++) {
            const int kc = kd * 8 + 2 * (l & 3);
            const int rb = w * 16 + (l >> 2);
            uint2 a01 = *(const uint2*)(sQ + rb * QS + kc);
            uint2 a23 = *(const uint2*)(sQ + (rb + 8) * QS + kc);
            #pragma unroll
            for (int ni = 0; ni < 4; ni++) {
                uint2 bv = *(const uint2*)(sK + (ni * 8 + (l >> 2)) * KS + kc);
                float* c = s[ni];
                mma_tf32(c[0], c[1], c[2], c[3], a01.x, a23.x, a01.y, a23.y, bv.x, bv.y);
            }
        }

        // ---- mask + scale (scale first; masked -> exactly -10000) ----
        const unsigned mw0 = g_adjbits[(b * Nn + rq) * (Nn / 32) + kt];
        const unsigned mw1 = g_adjbits[(b * Nn + rq + 8) * (Nn / 32) + kt];
        #pragma unroll
        for (int ni = 0; ni < 4; ni++) {
            const int k0 = ni * 8 + 2 * (l & 3);
            const unsigned b0 = (mw0 >> k0) & 3u;
            const unsigned b1 = (mw1 >> k0) & 3u;
            s[ni][0] = (b0 & 1u) ? s[ni][0] * 0.125f : -10000.f;
            s[ni][1] = (b0 & 2u) ? s[ni][1] * 0.125f : -10000.f;
            s[ni][2] = (b1 & 1u) ? s[ni][2] * 0.125f : -10000.f;
            s[ni][3] = (b1 & 2u) ? s[ni][3] * 0.125f : -10000.f;
        }

        // ---- online softmax (4-lane quad holds a full row) ----
        float mx0 = -1e30f, mx1 = -1e30f;
        #pragma unroll
        for (int ni = 0; ni < 4; ni++) {
            mx0 = fmaxf(mx0, fmaxf(s[ni][0], s[ni][1]));
            mx1 = fmaxf(mx1, fmaxf(s[ni][2], s[ni][3]));
        }
        mx0 = fmaxf(mx0, __shfl_xor_sync(0xffffffffu, mx0, 1));
        mx0 = fmaxf(mx0, __shfl_xor_sync(0xffffffffu, mx0, 2));
        mx1 = fmaxf(mx1, __shfl_xor_sync(0xffffffffu, mx1, 1));
        mx1 = fmaxf(mx1, __shfl_xor_sync(0xffffffffu, mx1, 2));
        const float nm0 = fmaxf(m0s, mx0);
        const float nm1 = fmaxf(m1s, mx1);
        const float al0 = __expf(m0s - nm0);
        const float al1 = __expf(m1s - nm1);
        m0s = nm0; m1s = nm1;
        #pragma unroll
        for (int nj = 0; nj < 8; nj++) {
            o[nj][0] *= al0; o[nj][1] *= al0;
            o[nj][2] *= al1; o[nj][3] *= al1;
        }

        // ---- P = exp(s - m); C-frag IS the PV A-frag (reorder p0,p2,p1,p3) ----
        float sum0 = 0.f, sum1 = 0.f;
        #pragma unroll
        for (int g = 0; g < 4; g++) {
            const float p0 = __expf(s[g][0] - nm0);
            const float p1 = __expf(s[g][1] - nm0);
            const float p2 = __expf(s[g][2] - nm1);
            const float p3 = __expf(s[g][3] - nm1);
            sum0 += p0 + p1; sum1 += p2 + p3;
            const unsigned a0 = __float_as_uint(p0);
            const unsigned a1 = __float_as_uint(p2);
            const unsigned a2 = __float_as_uint(p1);
            const unsigned a3 = __float_as_uint(p3);
            const int kc = g * 8 + 2 * (l & 3);
            #pragma unroll
            for (int nj = 0; nj < 8; nj++) {
                uint2 bv = *(const uint2*)(sV + (nj * 8 + (l >> 2)) * VS + kc);
                float* c = o[nj];
                mma_tf32(c[0], c[1], c[2], c[3], a0, a1, a2, a3, bv.x, bv.y);
            }
        }
        sum0 += __shfl_xor_sync(0xffffffffu, sum0, 1);
        sum0 += __shfl_xor_sync(0xffffffffu, sum0, 2);
        sum1 += __shfl_xor_sync(0xffffffffu, sum1, 1);
        sum1 += __shfl_xor_sync(0xffffffffu, sum1, 2);
        l0s = l0s * al0 + sum0;
        l1s = l1s * al1 + sum1;

        __syncthreads();   // stage consumed before reload
    }

    // ---- epilogue: ctx fp32 [B,N,D] head-concat ----
    const float inv0 = 1.f / l0s;
    const float inv1 = 1.f / l1s;
    const int row0g = b * Nn + rq;
    #pragma unroll
    for (int nj = 0; nj < 8; nj++) {
        const int c = h * HDIM + nj * 8 + 2 * (l & 3);
        float2 v0; v0.x = o[nj][0] * inv0; v0.y = o[nj][1] * inv0;
        float2 v1; v1.x = o[nj][2] * inv1; v1.y = o[nj][3] * inv1;
        *(float2*)&g_c[row0g * Dd + c]       = v0;
        *(float2*)&g_c[(row0g + 8) * Dd + c] = v1;
    }
}

// ---------------- LayerNorm over D=512 per row ----------------
__global__ void __launch_bounds__(256) ln_kernel(
    const float* __restrict__ gamma,
    const float* __restrict__ beta,
    float* __restrict__ out)
{
    const int row = blockIdx.x;
    const int t   = threadIdx.x;
    const float* __restrict__ y = g_y + row * Dd;

    float2 v = *(const float2*)&y[t * 2];
    float s = v.x + v.y;
    float q = v.x * v.x + v.y * v.y;
    #pragma unroll
    for (int o = 16; o > 0; o >>= 1) {
        s += __shfl_xor_sync(0xffffffffu, s, o);
        q += __shfl_xor_sync(0xffffffffu, q, o);
    }
    __shared__ float ssum[8], ssq[8];
    if ((t & 31) == 0) { ssum[t >> 5] = s; ssq[t >> 5] = q; }
    __syncthreads();
    float ts = 0.f, tq = 0.f;
    #pragma unroll
    for (int wv = 0; wv < 8; wv++) { ts += ssum[wv]; tq += ssq[wv]; }

    const float mean = ts * (1.f / 512.f);
    const float var  = tq * (1.f / 512.f) - mean * mean;
    const float inv  = rsqrtf(var + 1e-5f);

    float2 g  = *(const float2*)&gamma[t * 2];
    float2 bt = *(const float2*)&beta[t * 2];
    float2 o;
    o.x = (v.x - mean) * inv * g.x + bt.x;
    o.y = (v.y - mean) * inv * g.y + bt.y;
    *(float2*)&out[row * Dd + t * 2] = o;
}

// ---------------------------------------------------------------------------
extern "C" void kernel_launch(void* const* d_in, const int* in_sizes, int n_in,
                              void* d_out, int out_size)
{
    const float* x     = (const float*)d_in[0];
    const int*   adj   = (const int*)  d_in[1];
    const float* wq    = (const float*)d_in[2];
    const float* wk    = (const float*)d_in[3];
    const float* wv    = (const float*)d_in[4];
    const float* wo    = (const float*)d_in[5];
    const float* bo    = (const float*)d_in[6];
    const float* gamma = (const float*)d_in[7];
    const float* beta  = (const float*)d_in[8];
    float* out = (float*)d_out;

    const int gemm_smem = 2 * GSTAGEF * 4;                  // 61440 B
    const int attn_smem = (AQF + 2 * ASTAGEF) * 4;          // 75776 B
    cudaFuncSetAttribute(gemm_tf32,  cudaFuncAttributeMaxDynamicSharedMemorySize, gemm_smem);
    cudaFuncSetAttribute(attn_kernel, cudaFuncAttributeMaxDynamicSharedMemorySize, attn_smem);

    prep_kernel<<<1024, 256>>>(adj);
    gemm_tf32<<<dim3(8, 64, 3), 256, gemm_smem>>>(-1, x, wq, wk, wv, nullptr, nullptr);
    attn_kernel<<<dim3(8, Hh, Bb), 256, attn_smem>>>();
    gemm_tf32<<<dim3(8, 64, 1), 256, gemm_smem>>>(3, nullptr, wo, nullptr, nullptr, x, bo);
    ln_kernel<<<Bb * Nn, 256>>>(gamma, beta, out);
}

// round 7
// speedup vs baseline: 3.1307x; 1.0526x over previous
#include <cuda_runtime.h>

#define Bb 8
#define Nn 1024
#define Dd 512
#define Hh 8
#define HDIM 64

// ---------------- device scratch (allocation-free rule) ----------------
__device__ __align__(256) float g_q [Bb*Hh*Nn*HDIM];
__device__ __align__(256) float g_k [Bb*Hh*Nn*HDIM];
__device__ __align__(256) float g_vt[Bb*Hh*HDIM*Nn];   // [B,H,hd,N]
__device__ __align__(256) float g_c [Bb*Nn*Dd];        // attention context
__device__ __align__(256) float g_y [Bb*Nn*Dd];
__device__ __align__(256) unsigned g_adjbits[Bb*Nn*Nn/32];

// ---------------- helpers ----------------
// tf32 mma, k-dim mapping: physical k pair (2t,2t+1) fed as mma-k (t, t+4) on BOTH
// operands -> dot product order-permuted but exact. Lets every fragment be one LDS.64.
__device__ __forceinline__ void mma_tf32(float& c0, float& c1, float& c2, float& c3,
                                         unsigned a0, unsigned a1, unsigned a2, unsigned a3,
                                         unsigned b0, unsigned b1) {
    asm volatile(
        "mma.sync.aligned.m16n8k8.row.col.f32.tf32.tf32.f32 "
        "{%0,%1,%2,%3},{%4,%5,%6,%7},{%8,%9},{%0,%1,%2,%3};\n"
        : "+f"(c0), "+f"(c1), "+f"(c2), "+f"(c3)
        : "r"(a0), "r"(a1), "r"(a2), "r"(a3), "r"(b0), "r"(b1));
}
__device__ __forceinline__ void cp16(void* dst_smem, const void* src) {
    unsigned d = (unsigned)__cvta_generic_to_shared(dst_smem);
    asm volatile("cp.async.cg.shared.global [%0], [%1], 16;\n" :: "r"(d), "l"(src));
}
__device__ __forceinline__ void cp_commit() { asm volatile("cp.async.commit_group;\n" ::); }
__device__ __forceinline__ void cp_wait0()  { asm volatile("cp.async.wait_group 0;\n" ::); }

// ---------------- prologue: adj -> bitmask ----------------
__global__ void __launch_bounds__(256) prep_kernel(const int* __restrict__ adj) {
    const int idx = blockIdx.x * 256 + threadIdx.x;   // < B*N*N/32
    const int4* p = (const int4*)(adj + idx * 32);
    unsigned w = 0;
    #pragma unroll
    for (int j = 0; j < 8; j++) {
        int4 a = p[j];
        w |= (a.x != 0 ? 1u : 0u) << (j * 4 + 0);
        w |= (a.y != 0 ? 1u : 0u) << (j * 4 + 1);
        w |= (a.z != 0 ? 1u : 0u) << (j * 4 + 2);
        w |= (a.w != 0 ? 1u : 0u) << (j * 4 + 3);
    }
    g_adjbits[idx] = w;
}

// ---------------- tf32 GEMM: C[128x64] = A[128xK] @ W[NxK]^T ----------------
// modes: 0=Q out, 1=K out, 2=V out (transposed [B,H,hd,N]), 3=O-proj (+x+bo -> g_y)
#define GST 40                       // A/B smem row stride (words); 40 == 8 mod 32 -> conflict-free LDS.64
#define GSTAGEF (128*GST + 64*GST)   // floats per stage = 7680 (30720 B)
__global__ void __launch_bounds__(256, 3) gemm_tf32(int mode_p,
    const float* __restrict__ Ax,
    const float* __restrict__ W0, const float* __restrict__ W1, const float* __restrict__ W2,
    const float* __restrict__ xres, const float* __restrict__ bo)
{
    extern __shared__ float smg[];

    const int mode = (mode_p < 0) ? blockIdx.z : mode_p;
    const float* __restrict__ A = (mode == 3) ? g_c : Ax;
    const float* __restrict__ W = (mode_p < 0)
        ? (blockIdx.z == 0 ? W0 : (blockIdx.z == 1 ? W1 : W2)) : W0;

    const int m0 = blockIdx.y * 128;
    const int n0 = blockIdx.x * 64;
    const int t  = threadIdx.x;
    const int l  = t & 31;
    const int wid = t >> 5;
    const int wm = wid >> 1;   // 0..3
    const int wn = wid & 1;    // 0..1

    float acc[2][4][4];
    #pragma unroll
    for (int mi = 0; mi < 2; mi++)
        #pragma unroll
        for (int ni = 0; ni < 4; ni++)
            #pragma unroll
            for (int c = 0; c < 4; c++) acc[mi][ni][c] = 0.f;

    auto load_stage = [&](int s, int k0) {
        float* sA = smg + s * GSTAGEF;
        float* sB = sA + 128 * GST;
        #pragma unroll
        for (int it = 0; it < 4; it++) {
            const int u = t + it * 256;
            const int row = u >> 3;
            const int ch  = (u & 7) * 4;
            cp16(&sA[row * GST + ch], &A[(m0 + row) * Dd + k0 + ch]);
        }
        #pragma unroll
        for (int it = 0; it < 2; it++) {
            const int u = t + it * 256;
            const int row = u >> 3;
            const int ch  = (u & 7) * 4;
            cp16(&sB[row * GST + ch], &W[(n0 + row) * Dd + k0 + ch]);
        }
    };

    load_stage(0, 0);
    cp_commit();

    for (int ki = 0; ki < 16; ki++) {
        cp_wait0();
        __syncthreads();
        if (ki < 15) { load_stage((ki + 1) & 1, (ki + 1) * 32); cp_commit(); }

        const float* sA = smg + (ki & 1) * GSTAGEF;
        const float* sB = sA + 128 * GST;

        #pragma unroll
        for (int ks = 0; ks < 4; ks++) {
            const int kc = ks * 8 + 2 * (l & 3);
            unsigned af[2][4];
            #pragma unroll
            for (int mi = 0; mi < 2; mi++) {
                const int rb = wm * 32 + mi * 16 + (l >> 2);
                uint2 a01 = *(const uint2*)(sA + rb * GST + kc);
                uint2 a23 = *(const uint2*)(sA + (rb + 8) * GST + kc);
                af[mi][0] = a01.x; af[mi][1] = a23.x; af[mi][2] = a01.y; af[mi][3] = a23.y;
            }
            #pragma unroll
            for (int ni = 0; ni < 4; ni++) {
                const int nb = wn * 32 + ni * 8 + (l >> 2);
                uint2 bv = *(const uint2*)(sB + nb * GST + kc);
                #pragma unroll
                for (int mi = 0; mi < 2; mi++) {
                    float* c = acc[mi][ni];
                    mma_tf32(c[0], c[1], c[2], c[3],
                             af[mi][0], af[mi][1], af[mi][2], af[mi][3], bv.x, bv.y);
                }
            }
        }
    }

    // -------- epilogue --------
    if (mode == 0 || mode == 1) {
        float* O = (mode == 0) ? g_q : g_k;
        const int h = blockIdx.x;
        #pragma unroll
        for (int mi = 0; mi < 2; mi++)
            #pragma unroll
            for (int ni = 0; ni < 4; ni++) {
                const int m  = m0 + wm * 32 + mi * 16 + (l >> 2);
                const int hd = wn * 32 + ni * 8 + 2 * (l & 3);
                const float* c = acc[mi][ni];
                #pragma unroll
                for (int rr = 0; rr < 2; rr++) {
                    const int mr = m + rr * 8;
                    const int b  = mr >> 10;
                    const int n  = mr & 1023;
                    float2 v; v.x = c[rr * 2 + 0]; v.y = c[rr * 2 + 1];
                    *(float2*)&O[(((b * Hh + h) * Nn) + n) * HDIM + hd] = v;
                }
            }
    } else if (mode == 2) {
        // bounce through smem (stride 72 -> conflict-free), emit transposed [B,H,hd,N]
        __syncthreads();
        float* sf = smg;   // 128 x 72 floats
        #pragma unroll
        for (int mi = 0; mi < 2; mi++)
            #pragma unroll
            for (int ni = 0; ni < 4; ni++) {
                const int mb = wm * 32 + mi * 16 + (l >> 2);
                const int cc = wn * 32 + ni * 8 + 2 * (l & 3);
                const float* c = acc[mi][ni];
                float2 v0; v0.x = c[0]; v0.y = c[1];
                float2 v1; v1.x = c[2]; v1.y = c[3];
                *(float2*)(sf + mb * 72 + cc)       = v0;
                *(float2*)(sf + (mb + 8) * 72 + cc) = v1;
            }
        __syncthreads();
        const int h = blockIdx.x;
        const int b = m0 >> 10;
        const int ntok0 = m0 & 1023;
        const int hd = t & 63;
        const int tg = t >> 6;          // 0..3 (32 tokens each)
        const int gbase = (((b * Hh + h) * HDIM) + hd) * Nn + ntok0 + tg * 32;
        #pragma unroll
        for (int j4 = 0; j4 < 8; j4++) {
            float4 v;
            v.x = sf[(tg * 32 + j4 * 4 + 0) * 72 + hd];
            v.y = sf[(tg * 32 + j4 * 4 + 1) * 72 + hd];
            v.z = sf[(tg * 32 + j4 * 4 + 2) * 72 + hd];
            v.w = sf[(tg * 32 + j4 * 4 + 3) * 72 + hd];
            *(float4*)&g_vt[gbase + j4 * 4] = v;
        }
    } else {
        // oproj: y = acc + x + bo  -> g_y (fp32)
        #pragma unroll
        for (int mi = 0; mi < 2; mi++)
            #pragma unroll
            for (int ni = 0; ni < 4; ni++) {
                const int m  = m0 + wm * 32 + mi * 16 + (l >> 2);
                const int gc = n0 + wn * 32 + ni * 8 + 2 * (l & 3);
                const float* c = acc[mi][ni];
                float2 bv = *(const float2*)&bo[gc];
                #pragma unroll
                for (int rr = 0; rr < 2; rr++) {
                    const int mr = m + rr * 8;
                    float2 xv = *(const float2*)&xres[mr * Dd + gc];
                    float2 o;
                    o.x = c[rr * 2 + 0] + xv.x + bv.x;
                    o.y = c[rr * 2 + 1] + xv.y + bv.y;
                    *(float2*)&g_y[mr * Dd + gc] = o;
                }
            }
    }
}

// ---------------- flash attention, tf32 mma, max-free softmax ----------------
// 256 threads, 8 warps x 16 q rows; 32-key tiles double-buffered, ONE barrier/iter.
// Softmax: p = exp2(s * log2(e)/8); masked -> exp2(-3000) = 0 (identical to ref's
// fp32 underflow of exp(-10000 - m)). Row sums kept as per-lane partials, reduced
// once after the loop. Only loop-carried state: O accumulators (inside mma pipe).
#define QS 72
#define KS 72
#define VS 40
#define ASTAGEF (32*KS + 64*VS)      // 4864 floats per stage
#define AQF (128*QS)                 // 9216 floats
__global__ void __launch_bounds__(256, 3) attn_kernel() {
    extern __shared__ float sma[];
    float* sQ = sma;                         // 128 x 72

    const int qt = blockIdx.x;   // 0..7
    const int h  = blockIdx.y;
    const int b  = blockIdx.z;
    const int bh = b * Hh + h;
    const int t  = threadIdx.x;
    const int l  = t & 31;
    const int w  = t >> 5;                   // 16 q rows per warp
    const int rq = qt * 128 + w * 16 + (l >> 2);   // q row0 (row1 = +8)

    // Q tile -> smem (async, part of group 0)
    #pragma unroll
    for (int it = 0; it < 8; it++) {
        const int u = t + it * 256;
        const int row = u >> 4;
        const int ch  = (u & 15) * 4;
        cp16(&sQ[row * QS + ch], &g_q[((bh * Nn) + qt * 128 + row) * HDIM + ch]);
    }

    auto load_stage = [&](int s, int kt) {
        float* sK = sma + AQF + s * ASTAGEF;
        float* sV = sK + 32 * KS;
        #pragma unroll
        for (int it = 0; it < 2; it++) {
            const int u = t + it * 256;
            { const int row = u >> 4, ch = (u & 15) * 4;
              cp16(&sK[row * KS + ch], &g_k[((bh * Nn) + kt * 32 + row) * HDIM + ch]); }
            { const int row = u >> 3, ch = (u & 7) * 4;
              cp16(&sV[row * VS + ch], &g_vt[((bh * HDIM) + row) * Nn + kt * 32 + ch]); }
        }
    };

    load_stage(0, 0);
    cp_commit();

    float o[8][4];
    #pragma unroll
    for (int nj = 0; nj < 8; nj++)
        #pragma unroll
        for (int c = 0; c < 4; c++) o[nj][c] = 0.f;
    float l0p = 0.f, l1p = 0.f;              // per-lane partial row sums

    const float SC = 0.1803368867f;          // log2(e) / 8

    for (int kt = 0; kt < 32; kt++) {
        cp_wait0();
        __syncthreads();
        if (kt < 31) { load_stage((kt + 1) & 1, kt + 1); cp_commit(); }

        const float* sK = sma + AQF + (kt & 1) * ASTAGEF;
        const float* sV = sK + 32 * KS;

        // ---- scores S[16 x 32] per warp ----
        float s[4][4];
        #pragma unroll
        for (int ni = 0; ni < 4; ni++)
            #pragma unroll
            for (int c = 0; c < 4; c++) s[ni][c] = 0.f;

        #pragma unroll
        for (int kd = 0; kd < 8; kd++) {
            const int kc = kd * 8 + 2 * (l & 3);
            const int rb = w * 16 + (l >> 2);
            uint2 a01 = *(const uint2*)(sQ + rb * QS + kc);
            uint2 a23 = *(const uint2*)(sQ + (rb + 8) * QS + kc);
            #pragma unroll
            for (int ni = 0; ni < 4; ni++) {
                uint2 bv = *(const uint2*)(sK + (ni * 8 + (l >> 2)) * KS + kc);
                float* c = s[ni];
                mma_tf32(c[0], c[1], c[2], c[3], a01.x, a23.x, a01.y, a23.y, bv.x, bv.y);
            }
        }

        // ---- mask + scale into log2 domain (masked -> -3000 -> exp2 = 0) ----
        const unsigned mw0 = g_adjbits[(b * Nn + rq) * (Nn / 32) + kt];
        const unsigned mw1 = g_adjbits[(b * Nn + rq + 8) * (Nn / 32) + kt];
        #pragma unroll
        for (int ni = 0; ni < 4; ni++) {
            const int k0 = ni * 8 + 2 * (l & 3);
            const unsigned b0 = (mw0 >> k0) & 3u;
            const unsigned b1 = (mw1 >> k0) & 3u;
            s[ni][0] = (b0 & 1u) ? s[ni][0] * SC : -3000.f;
            s[ni][1] = (b0 & 2u) ? s[ni][1] * SC : -3000.f;
            s[ni][2] = (b1 & 1u) ? s[ni][2] * SC : -3000.f;
            s[ni][3] = (b1 & 2u) ? s[ni][3] * SC : -3000.f;
        }

        // ---- P = exp2(s); C-frag IS the PV A-frag (reorder p0,p2,p1,p3) ----
        #pragma unroll
        for (int g = 0; g < 4; g++) {
            const float p0 = exp2f(s[g][0]);
            const float p1 = exp2f(s[g][1]);
            const float p2 = exp2f(s[g][2]);
            const float p3 = exp2f(s[g][3]);
            l0p += p0 + p1; l1p += p2 + p3;
            const unsigned a0 = __float_as_uint(p0);
            const unsigned a1 = __float_as_uint(p2);
            const unsigned a2 = __float_as_uint(p1);
            const unsigned a3 = __float_as_uint(p3);
            const int kc = g * 8 + 2 * (l & 3);
            #pragma unroll
            for (int nj = 0; nj < 8; nj++) {
                uint2 bv = *(const uint2*)(sV + (nj * 8 + (l >> 2)) * VS + kc);
                float* c = o[nj];
                mma_tf32(c[0], c[1], c[2], c[3], a0, a1, a2, a3, bv.x, bv.y);
            }
        }
    }

    // ---- final row-sum reduction (once, not per tile) ----
    l0p += __shfl_xor_sync(0xffffffffu, l0p, 1);
    l0p += __shfl_xor_sync(0xffffffffu, l0p, 2);
    l1p += __shfl_xor_sync(0xffffffffu, l1p, 1);
    l1p += __shfl_xor_sync(0xffffffffu, l1p, 2);
    const float inv0 = 1.f / l0p;
    const float inv1 = 1.f / l1p;

    // ---- epilogue: ctx fp32 [B,N,D] head-concat ----
    const int row0g = b * Nn + rq;
    #pragma unroll
    for (int nj = 0; nj < 8; nj++) {
        const int c = h * HDIM + nj * 8 + 2 * (l & 3);
        float2 v0; v0.x = o[nj][0] * inv0; v0.y = o[nj][1] * inv0;
        float2 v1; v1.x = o[nj][2] * inv1; v1.y = o[nj][3] * inv1;
        *(float2*)&g_c[row0g * Dd + c]       = v0;
        *(float2*)&g_c[(row0g + 8) * Dd + c] = v1;
    }
}

// ---------------- LayerNorm over D=512 per row ----------------
__global__ void __launch_bounds__(256) ln_kernel(
    const float* __restrict__ gamma,
    const float* __restrict__ beta,
    float* __restrict__ out)
{
    const int row = blockIdx.x;
    const int t   = threadIdx.x;
    const float* __restrict__ y = g_y + row * Dd;

    float2 v = *(const float2*)&y[t * 2];
    float s = v.x + v.y;
    float q = v.x * v.x + v.y * v.y;
    #pragma unroll
    for (int o = 16; o > 0; o >>= 1) {
        s += __shfl_xor_sync(0xffffffffu, s, o);
        q += __shfl_xor_sync(0xffffffffu, q, o);
    }
    __shared__ float ssum[8], ssq[8];
    if ((t & 31) == 0) { ssum[t >> 5] = s; ssq[t >> 5] = q; }
    __syncthreads();
    float ts = 0.f, tq = 0.f;
    #pragma unroll
    for (int wv = 0; wv < 8; wv++) { ts += ssum[wv]; tq += ssq[wv]; }

    const float mean = ts * (1.f / 512.f);
    const float var  = tq * (1.f / 512.f) - mean * mean;
    const float inv  = rsqrtf(var + 1e-5f);

    float2 g  = *(const float2*)&gamma[t * 2];
    float2 bt = *(const float2*)&beta[t * 2];
    float2 o;
    o.x = (v.x - mean) * inv * g.x + bt.x;
    o.y = (v.y - mean) * inv * g.y + bt.y;
    *(float2*)&out[row * Dd + t * 2] = o;
}

// ---------------------------------------------------------------------------
extern "C" void kernel_launch(void* const* d_in, const int* in_sizes, int n_in,
                              void* d_out, int out_size)
{
    const float* x     = (const float*)d_in[0];
    const int*   adj   = (const int*)  d_in[1];
    const float* wq    = (const float*)d_in[2];
    const float* wk    = (const float*)d_in[3];
    const float* wv    = (const float*)d_in[4];
    const float* wo    = (const float*)d_in[5];
    const float* bo    = (const float*)d_in[6];
    const float* gamma = (const float*)d_in[7];
    const float* beta  = (const float*)d_in[8];
    float* out = (float*)d_out;

    const int gemm_smem = 2 * GSTAGEF * 4;                  // 61440 B
    const int attn_smem = (AQF + 2 * ASTAGEF) * 4;          // 75776 B
    cudaFuncSetAttribute(gemm_tf32,  cudaFuncAttributeMaxDynamicSharedMemorySize, gemm_smem);
    cudaFuncSetAttribute(attn_kernel, cudaFuncAttributeMaxDynamicSharedMemorySize, attn_smem);

    prep_kernel<<<1024, 256>>>(adj);
    gemm_tf32<<<dim3(8, 64, 3), 256, gemm_smem>>>(-1, x, wq, wk, wv, nullptr, nullptr);
    attn_kernel<<<dim3(8, Hh, Bb), 256, attn_smem>>>();
    gemm_tf32<<<dim3(8, 64, 1), 256, gemm_smem>>>(3, nullptr, wo, nullptr, nullptr, x, bo);
    ln_kernel<<<Bb * Nn, 256>>>(gamma, beta, out);
}

// round 9
// speedup vs baseline: 3.2593x; 1.0411x over previous
#include <cuda_runtime.h>

#define Bb 8
#define Nn 1024
#define Dd 512
#define Hh 8
#define HDIM 64

// ---------------- device scratch (allocation-free rule) ----------------
__device__ __align__(256) float g_q [Bb*Hh*Nn*HDIM];
__device__ __align__(256) float g_k [Bb*Hh*Nn*HDIM];
__device__ __align__(256) float g_vt[Bb*Hh*HDIM*Nn];   // [B,H,hd,N]
__device__ __align__(256) float g_c [Bb*Nn*Dd];        // attention context
__device__ __align__(256) float g_y [Bb*Nn*Dd];
__device__ __align__(256) unsigned g_adjbits[Bb*Nn*Nn/32];

// ---------------- helpers ----------------
// tf32 mma, k-dim mapping: physical k pair (2t,2t+1) fed as mma-k (t, t+4) on BOTH
// operands -> dot product order-permuted but exact. Lets every fragment be one LDS.64.
__device__ __forceinline__ void mma_tf32(float& c0, float& c1, float& c2, float& c3,
                                         unsigned a0, unsigned a1, unsigned a2, unsigned a3,
                                         unsigned b0, unsigned b1) {
    asm volatile(
        "mma.sync.aligned.m16n8k8.row.col.f32.tf32.tf32.f32 "
        "{%0,%1,%2,%3},{%4,%5,%6,%7},{%8,%9},{%0,%1,%2,%3};\n"
        : "+f"(c0), "+f"(c1), "+f"(c2), "+f"(c3)
        : "r"(a0), "r"(a1), "r"(a2), "r"(a3), "r"(b0), "r"(b1));
}
__device__ __forceinline__ void cp16(void* dst_smem, const void* src) {
    unsigned d = (unsigned)__cvta_generic_to_shared(dst_smem);
    asm volatile("cp.async.cg.shared.global [%0], [%1], 16;\n" :: "r"(d), "l"(src));
}
__device__ __forceinline__ void cp_commit() { asm volatile("cp.async.commit_group;\n" ::); }
__device__ __forceinline__ void cp_wait0()  { asm volatile("cp.async.wait_group 0;\n" ::); }

// ---------------- prologue: adj -> bitmask ----------------
__global__ void __launch_bounds__(256) prep_kernel(const int* __restrict__ adj) {
    const int idx = blockIdx.x * 256 + threadIdx.x;   // < B*N*N/32
    const int4* p = (const int4*)(adj + idx * 32);
    unsigned w = 0;
    #pragma unroll
    for (int j = 0; j < 8; j++) {
        int4 a = p[j];
        w |= (a.x != 0 ? 1u : 0u) << (j * 4 + 0);
        w |= (a.y != 0 ? 1u : 0u) << (j * 4 + 1);
        w |= (a.z != 0 ? 1u : 0u) << (j * 4 + 2);
        w |= (a.w != 0 ? 1u : 0u) << (j * 4 + 3);
    }
    g_adjbits[idx] = w;
}

// ---------------- tf32 GEMM: C[128x64] = A[128xK] @ W[NxK]^T ----------------
// modes: 0=Q out, 1=K out, 2=V out (transposed [B,H,hd,N]), 3=O-proj (+x+bo -> g_y)
#define GST 40                       // A/B smem row stride (words); 40 == 8 mod 32 -> conflict-free LDS.64
#define GSTAGEF (128*GST + 64*GST)   // floats per stage = 7680 (30720 B)
__global__ void __launch_bounds__(256, 3) gemm_tf32(int mode_p,
    const float* __restrict__ Ax,
    const float* __restrict__ W0, const float* __restrict__ W1, const float* __restrict__ W2,
    const float* __restrict__ xres, const float* __restrict__ bo)
{
    extern __shared__ float smg[];

    const int mode = (mode_p < 0) ? blockIdx.z : mode_p;
    const float* __restrict__ A = (mode == 3) ? g_c : Ax;
    const float* __restrict__ W = (mode_p < 0)
        ? (blockIdx.z == 0 ? W0 : (blockIdx.z == 1 ? W1 : W2)) : W0;

    const int m0 = blockIdx.y * 128;
    const int n0 = blockIdx.x * 64;
    const int t  = threadIdx.x;
    const int l  = t & 31;
    const int wid = t >> 5;
    const int wm = wid >> 1;   // 0..3
    const int wn = wid & 1;    // 0..1

    float acc[2][4][4];
    #pragma unroll
    for (int mi = 0; mi < 2; mi++)
        #pragma unroll
        for (int ni = 0; ni < 4; ni++)
            #pragma unroll
            for (int c = 0; c < 4; c++) acc[mi][ni][c] = 0.f;

    auto load_stage = [&](int s, int k0) {
        float* sA = smg + s * GSTAGEF;
        float* sB = sA + 128 * GST;
        #pragma unroll
        for (int it = 0; it < 4; it++) {
            const int u = t + it * 256;
            const int row = u >> 3;
            const int ch  = (u & 7) * 4;
            cp16(&sA[row * GST + ch], &A[(m0 + row) * Dd + k0 + ch]);
        }
        #pragma unroll
        for (int it = 0; it < 2; it++) {
            const int u = t + it * 256;
            const int row = u >> 3;
            const int ch  = (u & 7) * 4;
            cp16(&sB[row * GST + ch], &W[(n0 + row) * Dd + k0 + ch]);
        }
    };

    load_stage(0, 0);
    cp_commit();

    for (int ki = 0; ki < 16; ki++) {
        cp_wait0();
        __syncthreads();
        if (ki < 15) { load_stage((ki + 1) & 1, (ki + 1) * 32); cp_commit(); }

        const float* sA = smg + (ki & 1) * GSTAGEF;
        const float* sB = sA + 128 * GST;

        #pragma unroll
        for (int ks = 0; ks < 4; ks++) {
            const int kc = ks * 8 + 2 * (l & 3);
            unsigned af[2][4];
            #pragma unroll
            for (int mi = 0; mi < 2; mi++) {
                const int rb = wm * 32 + mi * 16 + (l >> 2);
                uint2 a01 = *(const uint2*)(sA + rb * GST + kc);
                uint2 a23 = *(const uint2*)(sA + (rb + 8) * GST + kc);
                af[mi][0] = a01.x; af[mi][1] = a23.x; af[mi][2] = a01.y; af[mi][3] = a23.y;
            }
            #pragma unroll
            for (int ni = 0; ni < 4; ni++) {
                const int nb = wn * 32 + ni * 8 + (l >> 2);
                uint2 bv = *(const uint2*)(sB + nb * GST + kc);
                #pragma unroll
                for (int mi = 0; mi < 2; mi++) {
                    float* c = acc[mi][ni];
                    mma_tf32(c[0], c[1], c[2], c[3],
                             af[mi][0], af[mi][1], af[mi][2], af[mi][3], bv.x, bv.y);
                }
            }
        }
    }

    // -------- epilogue --------
    if (mode == 0 || mode == 1) {
        float* O = (mode == 0) ? g_q : g_k;
        const int h = blockIdx.x;
        #pragma unroll
        for (int mi = 0; mi < 2; mi++)
            #pragma unroll
            for (int ni = 0; ni < 4; ni++) {
                const int m  = m0 + wm * 32 + mi * 16 + (l >> 2);
                const int hd = wn * 32 + ni * 8 + 2 * (l & 3);
                const float* c = acc[mi][ni];
                #pragma unroll
                for (int rr = 0; rr < 2; rr++) {
                    const int mr = m + rr * 8;
                    const int b  = mr >> 10;
                    const int n  = mr & 1023;
                    float2 v; v.x = c[rr * 2 + 0]; v.y = c[rr * 2 + 1];
                    *(float2*)&O[(((b * Hh + h) * Nn) + n) * HDIM + hd] = v;
                }
            }
    } else if (mode == 2) {
        // bounce through smem (stride 72 -> conflict-free), emit transposed [B,H,hd,N]
        __syncthreads();
        float* sf = smg;   // 128 x 72 floats
        #pragma unroll
        for (int mi = 0; mi < 2; mi++)
            #pragma unroll
            for (int ni = 0; ni < 4; ni++) {
                const int mb = wm * 32 + mi * 16 + (l >> 2);
                const int cc = wn * 32 + ni * 8 + 2 * (l & 3);
                const float* c = acc[mi][ni];
                float2 v0; v0.x = c[0]; v0.y = c[1];
                float2 v1; v1.x = c[2]; v1.y = c[3];
                *(float2*)(sf + mb * 72 + cc)       = v0;
                *(float2*)(sf + (mb + 8) * 72 + cc) = v1;
            }
        __syncthreads();
        const int h = blockIdx.x;
        const int b = m0 >> 10;
        const int ntok0 = m0 & 1023;
        const int hd = t & 63;
        const int tg = t >> 6;          // 0..3 (32 tokens each)
        const int gbase = (((b * Hh + h) * HDIM) + hd) * Nn + ntok0 + tg * 32;
        #pragma unroll
        for (int j4 = 0; j4 < 8; j4++) {
            float4 v;
            v.x = sf[(tg * 32 + j4 * 4 + 0) * 72 + hd];
            v.y = sf[(tg * 32 + j4 * 4 + 1) * 72 + hd];
            v.z = sf[(tg * 32 + j4 * 4 + 2) * 72 + hd];
            v.w = sf[(tg * 32 + j4 * 4 + 3) * 72 + hd];
            *(float4*)&g_vt[gbase + j4 * 4] = v;
        }
    } else {
        // oproj: y = acc + x + bo  -> g_y (fp32)
        #pragma unroll
        for (int mi = 0; mi < 2; mi++)
            #pragma unroll
            for (int ni = 0; ni < 4; ni++) {
                const int m  = m0 + wm * 32 + mi * 16 + (l >> 2);
                const int gc = n0 + wn * 32 + ni * 8 + 2 * (l & 3);
                const float* c = acc[mi][ni];
                float2 bv = *(const float2*)&bo[gc];
                #pragma unroll
                for (int rr = 0; rr < 2; rr++) {
                    const int mr = m + rr * 8;
                    float2 xv = *(const float2*)&xres[mr * Dd + gc];
                    float2 o;
                    o.x = c[rr * 2 + 0] + xv.x + bv.x;
                    o.y = c[rr * 2 + 1] + xv.y + bv.y;
                    *(float2*)&g_y[mr * Dd + gc] = o;
                }
            }
    }
}

// ---------------- flash attention, tf32 mma, M=32 rows/warp ----------------
// 256 threads, 8 warps x 32 q rows = 256-row Q tile -> grid 256 (== 1 wave @ 2 CTA/SM).
// K/V fragments amortized over 2 m16 tiles: LDS.64/mma = 0.75 (was 1.25).
// Max-free softmax: p = exp2(s*log2e/8); masked -> exp2(-3000) = +0.
#define QS 72
#define KS 72
#define VS 40
#define ASTAGEF (32*KS + 64*VS)      // 4864 floats per stage
#define AQF (256*QS)                 // 18432 floats
__global__ void __launch_bounds__(256, 2) attn_kernel() {
    extern __shared__ float sma[];
    float* sQ = sma;                         // 256 x 72

    const int qt = blockIdx.x;   // 0..3
    const int h  = blockIdx.y;
    const int b  = blockIdx.z;
    const int bh = b * Hh + h;
    const int t  = threadIdx.x;
    const int l  = t & 31;
    const int w  = t >> 5;                   // 32 q rows per warp
    const int rq = qt * 256 + w * 32 + (l >> 2);   // base q row (mi adds 16, +8 inside)

    // Q tile 256x64 -> smem (async, part of commit group 0)
    #pragma unroll
    for (int it = 0; it < 16; it++) {
        const int u = t + it * 256;
        const int row = u >> 4;
        const int ch  = (u & 15) * 4;
        cp16(&sQ[row * QS + ch], &g_q[((bh * Nn) + qt * 256 + row) * HDIM + ch]);
    }

    auto load_stage = [&](int s, int kt) {
        float* sK = sma + AQF + s * ASTAGEF;
        float* sV = sK + 32 * KS;
        #pragma unroll
        for (int it = 0; it < 2; it++) {
            const int u = t + it * 256;
            { const int row = u >> 4, ch = (u & 15) * 4;
              cp16(&sK[row * KS + ch], &g_k[((bh * Nn) + kt * 32 + row) * HDIM + ch]); }
            { const int row = u >> 3, ch = (u & 7) * 4;
              cp16(&sV[row * VS + ch], &g_vt[((bh * HDIM) + row) * Nn + kt * 32 + ch]); }
        }
    };

    load_stage(0, 0);
    cp_commit();

    float o[2][8][4];
    #pragma unroll
    for (int mi = 0; mi < 2; mi++)
        #pragma unroll
        for (int nj = 0; nj < 8; nj++)
            #pragma unroll
            for (int c = 0; c < 4; c++) o[mi][nj][c] = 0.f;
    float lp[2][2] = {{0.f, 0.f}, {0.f, 0.f}};     // per-lane partial row sums

    const float SC = 0.1803368867f;          // log2(e) / 8

    for (int kt = 0; kt < 32; kt++) {
        cp_wait0();
        __syncthreads();
        if (kt < 31) { load_stage((kt + 1) & 1, kt + 1); cp_commit(); }

        const float* sK = sma + AQF + (kt & 1) * ASTAGEF;
        const float* sV = sK + 32 * KS;

        // ---- scores S[32 x 32] per warp (2 m16 tiles) ----
        float s[2][4][4];
        #pragma unroll
        for (int mi = 0; mi < 2; mi++)
            #pragma unroll
            for (int ni = 0; ni < 4; ni++)
                #pragma unroll
                for (int c = 0; c < 4; c++) s[mi][ni][c] = 0.f;

        #pragma unroll
        for (int kd = 0; kd < 8; kd++) {
            const int kc = kd * 8 + 2 * (l & 3);
            unsigned af[2][4];
            #pragma unroll
            for (int mi = 0; mi < 2; mi++) {
                const int rb = w * 32 + mi * 16 + (l >> 2);
                uint2 a01 = *(const uint2*)(sQ + rb * QS + kc);
                uint2 a23 = *(const uint2*)(sQ + (rb + 8) * QS + kc);
                af[mi][0] = a01.x; af[mi][1] = a23.x; af[mi][2] = a01.y; af[mi][3] = a23.y;
            }
            #pragma unroll
            for (int ni = 0; ni < 4; ni++) {
                uint2 bv = *(const uint2*)(sK + (ni * 8 + (l >> 2)) * KS + kc);
                #pragma unroll
                for (int mi = 0; mi < 2; mi++) {
                    float* c = s[mi][ni];
                    mma_tf32(c[0], c[1], c[2], c[3],
                             af[mi][0], af[mi][1], af[mi][2], af[mi][3], bv.x, bv.y);
                }
            }
        }

        // ---- mask + scale into log2 domain (masked -> -3000 -> exp2 = +0) ----
        unsigned mw[2][2];
        #pragma unroll
        for (int mi = 0; mi < 2; mi++) {
            mw[mi][0] = g_adjbits[(b * Nn + rq + mi * 16) * (Nn / 32) + kt];
            mw[mi][1] = g_adjbits[(b * Nn + rq + mi * 16 + 8) * (Nn / 32) + kt];
        }
        #pragma unroll
        for (int mi = 0; mi < 2; mi++)
            #pragma unroll
            for (int ni = 0; ni < 4; ni++) {
                const int k0 = ni * 8 + 2 * (l & 3);
                const unsigned b0 = (mw[mi][0] >> k0) & 3u;
                const unsigned b1 = (mw[mi][1] >> k0) & 3u;
                float* c = s[mi][ni];
                c[0] = (b0 & 1u) ? c[0] * SC : -3000.f;
                c[1] = (b0 & 2u) ? c[1] * SC : -3000.f;
                c[2] = (b1 & 1u) ? c[2] * SC : -3000.f;
                c[3] = (b1 & 2u) ? c[3] * SC : -3000.f;
            }

        // ---- P = exp2(s); C-frag IS the PV A-frag (reorder p0,p2,p1,p3) ----
        #pragma unroll
        for (int g = 0; g < 4; g++) {
            unsigned pa[2][4];
            #pragma unroll
            for (int mi = 0; mi < 2; mi++) {
                const float p0 = exp2f(s[mi][g][0]);
                const float p1 = exp2f(s[mi][g][1]);
                const float p2 = exp2f(s[mi][g][2]);
                const float p3 = exp2f(s[mi][g][3]);
                lp[mi][0] += p0 + p1; lp[mi][1] += p2 + p3;
                pa[mi][0] = __float_as_uint(p0);
                pa[mi][1] = __float_as_uint(p2);
                pa[mi][2] = __float_as_uint(p1);
                pa[mi][3] = __float_as_uint(p3);
            }
            const int kc = g * 8 + 2 * (l & 3);
            #pragma unroll
            for (int nj = 0; nj < 8; nj++) {
                uint2 bv = *(const uint2*)(sV + (nj * 8 + (l >> 2)) * VS + kc);
                #pragma unroll
                for (int mi = 0; mi < 2; mi++) {
                    float* c = o[mi][nj];
                    mma_tf32(c[0], c[1], c[2], c[3],
                             pa[mi][0], pa[mi][1], pa[mi][2], pa[mi][3], bv.x, bv.y);
                }
            }
        }
    }

    // ---- final row-sum reduction (once) + epilogue ----
    #pragma unroll
    for (int mi = 0; mi < 2; mi++) {
        float l0 = lp[mi][0], l1 = lp[mi][1];
        l0 += __shfl_xor_sync(0xffffffffu, l0, 1);
        l0 += __shfl_xor_sync(0xffffffffu, l0, 2);
        l1 += __shfl_xor_sync(0xffffffffu, l1, 1);
        l1 += __shfl_xor_sync(0xffffffffu, l1, 2);
        const float inv0 = 1.f / l0;
        const float inv1 = 1.f / l1;
        const int row0g = b * Nn + rq + mi * 16;
        #pragma unroll
        for (int nj = 0; nj < 8; nj++) {
            const int c = h * HDIM + nj * 8 + 2 * (l & 3);
            const float* oc = o[mi][nj];
            float2 v0; v0.x = oc[0] * inv0; v0.y = oc[1] * inv0;
            float2 v1; v1.x = oc[2] * inv1; v1.y = oc[3] * inv1;
            *(float2*)&g_c[row0g * Dd + c]       = v0;
            *(float2*)&g_c[(row0g + 8) * Dd + c] = v1;
        }
    }
}

// ---------------- LayerNorm over D=512 per row ----------------
__global__ void __launch_bounds__(256) ln_kernel(
    const float* __restrict__ gamma,
    const float* __restrict__ beta,
    float* __restrict__ out)
{
    const int row = blockIdx.x;
    const int t   = threadIdx.x;
    const float* __restrict__ y = g_y + row * Dd;

    float2 v = *(const float2*)&y[t * 2];
    float s = v.x + v.y;
    float q = v.x * v.x + v.y * v.y;
    #pragma unroll
    for (int o = 16; o > 0; o >>= 1) {
        s += __shfl_xor_sync(0xffffffffu, s, o);
        q += __shfl_xor_sync(0xffffffffu, q, o);
    }
    __shared__ float ssum[8], ssq[8];
    if ((t & 31) == 0) { ssum[t >> 5] = s; ssq[t >> 5] = q; }
    __syncthreads();
    float ts = 0.f, tq = 0.f;
    #pragma unroll
    for (int wv = 0; wv < 8; wv++) { ts += ssum[wv]; tq += ssq[wv]; }

    const float mean = ts * (1.f / 512.f);
    const float var  = tq * (1.f / 512.f) - mean * mean;
    const float inv  = rsqrtf(var + 1e-5f);

    float2 g  = *(const float2*)&gamma[t * 2];
    float2 bt = *(const float2*)&beta[t * 2];
    float2 o;
    o.x = (v.x - mean) * inv * g.x + bt.x;
    o.y = (v.y - mean) * inv * g.y + bt.y;
    *(float2*)&out[row * Dd + t * 2] = o;
}

// ---------------------------------------------------------------------------
extern "C" void kernel_launch(void* const* d_in, const int* in_sizes, int n_in,
                              void* d_out, int out_size)
{
    const float* x     = (const float*)d_in[0];
    const int*   adj   = (const int*)  d_in[1];
    const float* wq    = (const float*)d_in[2];
    const float* wk    = (const float*)d_in[3];
    const float* wv    = (const float*)d_in[4];
    const float* wo    = (const float*)d_in[5];
    const float* bo    = (const float*)d_in[6];
    const float* gamma = (const float*)d_in[7];
    const float* beta  = (const float*)d_in[8];
    float* out = (float*)d_out;

    const int gemm_smem = 2 * GSTAGEF * 4;                  // 61440 B
    const int attn_smem = (AQF + 2 * ASTAGEF) * 4;          // 112640 B
    cudaFuncSetAttribute(gemm_tf32,  cudaFuncAttributeMaxDynamicSharedMemorySize, gemm_smem);
    cudaFuncSetAttribute(attn_kernel, cudaFuncAttributeMaxDynamicSharedMemorySize, attn_smem);

    prep_kernel<<<1024, 256>>>(adj);
    gemm_tf32<<<dim3(8, 64, 3), 256, gemm_smem>>>(-1, x, wq, wk, wv, nullptr, nullptr);
    attn_kernel<<<dim3(4, Hh, Bb), 256, attn_smem>>>();
    gemm_tf32<<<dim3(8, 64, 1), 256, gemm_smem>>>(3, nullptr, wo, nullptr, nullptr, x, bo);
    ln_kernel<<<Bb * Nn, 256>>>(gamma, beta, out);
}

// round 10
// speedup vs baseline: 4.9058x; 1.5052x over previous
#include <cuda_runtime.h>
#include <cuda_fp16.h>

#define Bb 8
#define Nn 1024
#define Dd 512
#define Hh 8
#define HDIM 64

// ---------------- device scratch (allocation-free rule) ----------------
__device__ __align__(256) __half g_xh[Bb*Nn*Dd];        // x in fp16
__device__ __align__(256) __half g_wh[4*Dd*Dd];         // wq,wk,wv,wo fp16
__device__ __align__(256) __half g_q [Bb*Hh*Nn*HDIM];
__device__ __align__(256) __half g_k [Bb*Hh*Nn*HDIM];
__device__ __align__(256) __half g_vt[Bb*Hh*HDIM*Nn];   // [B,H,hd,N], keys PERMUTED within 16-groups
__device__ __align__(256) __half g_c [Bb*Nn*Dd];        // attention context fp16
__device__ __align__(256) float  g_y [Bb*Nn*Dd];
__device__ __align__(256) unsigned g_adjbits[Bb*Nn*Nn/32];

// ---------------- helpers ----------------
// fp16 m16n8k16 mma. k-permutation: each uint2 (4 halfs at phys k 4j..4j+3) feeds
// logical k pairs {2j,2j+1} (low u32) and {8+2j,8+2j+1} (high u32), applied to BOTH
// operands -> dot product order-permuted but exact; every fragment is one LDS.64.
__device__ __forceinline__ void mma_f16(float& c0, float& c1, float& c2, float& c3,
                                        unsigned a0, unsigned a1, unsigned a2, unsigned a3,
                                        unsigned b0, unsigned b1) {
    asm volatile(
        "mma.sync.aligned.m16n8k16.row.col.f32.f16.f16.f32 "
        "{%0,%1,%2,%3},{%4,%5,%6,%7},{%8,%9},{%0,%1,%2,%3};\n"
        : "+f"(c0), "+f"(c1), "+f"(c2), "+f"(c3)
        : "r"(a0), "r"(a1), "r"(a2), "r"(a3), "r"(b0), "r"(b1));
}
__device__ __forceinline__ void cp16(void* dst_smem, const void* src) {
    unsigned d = (unsigned)__cvta_generic_to_shared(dst_smem);
    asm volatile("cp.async.cg.shared.global [%0], [%1], 16;\n" :: "r"(d), "l"(src));
}
__device__ __forceinline__ void cp_commit() { asm volatile("cp.async.commit_group;\n" ::); }
__device__ __forceinline__ void cp_wait0()  { asm volatile("cp.async.wait_group 0;\n" ::); }
__device__ __forceinline__ unsigned packh2(float lo, float hi) {
    __half2 h = __floats2half2_rn(lo, hi);          // .x = lo half (low addr)
    return *(unsigned*)&h;
}

// ---------------- fused prologue: x/w -> fp16, adj -> bitmask ----------------
__global__ void __launch_bounds__(256) prep_kernel(
    const float* __restrict__ x,
    const float* __restrict__ wq, const float* __restrict__ wk,
    const float* __restrict__ wv, const float* __restrict__ wo,
    const int* __restrict__ adj)
{
    const int blk = blockIdx.x;
    const int t   = threadIdx.x;
    if (blk < 4096) {                        // x: 8192*512 floats
        const int i = (blk * 256 + t) * 4;
        float4 v = *(const float4*)(x + i);
        uint2 o;
        o.x = packh2(v.x, v.y);
        o.y = packh2(v.z, v.w);
        *(uint2*)&g_xh[i] = o;
    } else if (blk < 5120) {                 // 4 weights: 512*512 each
        const int wsel = (blk - 4096) >> 8;
        const float* src = (wsel == 0) ? wq : (wsel == 1) ? wk : (wsel == 2) ? wv : wo;
        const int i = (((blk - 4096) & 255) * 256 + t) * 4;
        float4 v = *(const float4*)(src + i);
        uint2 o;
        o.x = packh2(v.x, v.y);
        o.y = packh2(v.z, v.w);
        *(uint2*)&g_wh[wsel * Dd * Dd + i] = o;
    } else {                                 // adj pack
        const int idx = (blk - 5120) * 256 + t;
        const int4* p = (const int4*)(adj + idx * 32);
        unsigned w = 0;
        #pragma unroll
        for (int j = 0; j < 8; j++) {
            int4 a = p[j];
            w |= (a.x != 0 ? 1u : 0u) << (j * 4 + 0);
            w |= (a.y != 0 ? 1u : 0u) << (j * 4 + 1);
            w |= (a.z != 0 ? 1u : 0u) << (j * 4 + 2);
            w |= (a.w != 0 ? 1u : 0u) << (j * 4 + 3);
        }
        g_adjbits[idx] = w;
    }
}

// ---------------- fp16 GEMM: C[128x64] = A[128xK] @ W[NxK]^T ----------------
// modes: 0=Q, 1=K, 2=V (transposed+key-permuted [B,H,hd,N]), 3=O-proj (+x+bo -> g_y)
// k-tile 64 halfs; smem rows: 64 halfs data + pad, u32 stride 40 (conflict-free uint2).
#define GSTU 40                       // u32 stride
#define GSTAGEU ((128+64)*GSTU)       // 7680 u32 = 30720 B per stage
__global__ void __launch_bounds__(256, 3) gemm_f16(int mode_p,
    const float* __restrict__ xres, const float* __restrict__ bo)
{
    extern __shared__ unsigned smg[];

    const int mode = (mode_p < 0) ? blockIdx.z : mode_p;
    const __half* __restrict__ A = (mode == 3) ? g_c : g_xh;
    const __half* __restrict__ W = g_wh + mode * Dd * Dd;

    const int m0 = blockIdx.y * 128;
    const int n0 = blockIdx.x * 64;
    const int t  = threadIdx.x;
    const int l  = t & 31;
    const int wid = t >> 5;
    const int wm = wid >> 1;   // 0..3
    const int wn = wid & 1;    // 0..1

    float acc[2][4][4];
    #pragma unroll
    for (int mi = 0; mi < 2; mi++)
        #pragma unroll
        for (int ni = 0; ni < 4; ni++)
            #pragma unroll
            for (int c = 0; c < 4; c++) acc[mi][ni][c] = 0.f;

    auto load_stage = [&](int s, int k0) {
        unsigned* sA = smg + s * GSTAGEU;
        unsigned* sB = sA + 128 * GSTU;
        #pragma unroll
        for (int it = 0; it < 4; it++) {     // A: 128 rows x 8 chunks of 16B
            const int u = t + it * 256;
            const int row = u >> 3;
            const int q   = u & 7;
            cp16(&sA[row * GSTU + q * 4], &A[(m0 + row) * Dd + k0 + q * 8]);
        }
        #pragma unroll
        for (int it = 0; it < 2; it++) {     // B: 64 rows x 8 chunks
            const int u = t + it * 256;
            const int row = u >> 3;
            const int q   = u & 7;
            cp16(&sB[row * GSTU + q * 4], &W[(n0 + row) * Dd + k0 + q * 8]);
        }
    };

    load_stage(0, 0);
    cp_commit();

    for (int ki = 0; ki < 8; ki++) {         // K=512, k-tile 64
        cp_wait0();
        __syncthreads();
        if (ki < 7) { load_stage((ki + 1) & 1, (ki + 1) * 64); cp_commit(); }

        const unsigned* sA = smg + (ki & 1) * GSTAGEU;
        const unsigned* sB = sA + 128 * GSTU;

        #pragma unroll
        for (int ks = 0; ks < 4; ks++) {     // 4 k16-slices
            const int kc = ks * 8 + 2 * (l & 3);
            unsigned af[2][4];
            #pragma unroll
            for (int mi = 0; mi < 2; mi++) {
                const int rb = wm * 32 + mi * 16 + (l >> 2);
                uint2 r0 = *(const uint2*)(sA + rb * GSTU + kc);
                uint2 r8 = *(const uint2*)(sA + (rb + 8) * GSTU + kc);
                af[mi][0] = r0.x; af[mi][1] = r8.x; af[mi][2] = r0.y; af[mi][3] = r8.y;
            }
            #pragma unroll
            for (int ni = 0; ni < 4; ni++) {
                const int nb = wn * 32 + ni * 8 + (l >> 2);
                uint2 bv = *(const uint2*)(sB + nb * GSTU + kc);
                #pragma unroll
                for (int mi = 0; mi < 2; mi++) {
                    float* c = acc[mi][ni];
                    mma_f16(c[0], c[1], c[2], c[3],
                            af[mi][0], af[mi][1], af[mi][2], af[mi][3], bv.x, bv.y);
                }
            }
        }
    }

    // -------- epilogue --------
    if (mode == 0 || mode == 1) {
        __half* O = (mode == 0) ? g_q : g_k;
        const int h = blockIdx.x;
        #pragma unroll
        for (int mi = 0; mi < 2; mi++)
            #pragma unroll
            for (int ni = 0; ni < 4; ni++) {
                const int m  = m0 + wm * 32 + mi * 16 + (l >> 2);
                const int hd = wn * 32 + ni * 8 + 2 * (l & 3);
                const float* c = acc[mi][ni];
                #pragma unroll
                for (int rr = 0; rr < 2; rr++) {
                    const int mr = m + rr * 8;
                    const int b  = mr >> 10;
                    const int n  = mr & 1023;
                    *(unsigned*)&O[(((b * Hh + h) * Nn) + n) * HDIM + hd] =
                        packh2(c[rr * 2 + 0], c[rr * 2 + 1]);
                }
            }
    } else if (mode == 2) {
        // bounce through smem fp32, emit transposed [B,H,hd,N] with key perm:
        // within each 16-token group, token r -> pos ((r&6)<<1)|(r&1)|((r&8)>>2)
        __syncthreads();
        float* sf = (float*)smg;   // 128 x 72 floats
        #pragma unroll
        for (int mi = 0; mi < 2; mi++)
            #pragma unroll
            for (int ni = 0; ni < 4; ni++) {
                const int mb = wm * 32 + mi * 16 + (l >> 2);
                const int cc = wn * 32 + ni * 8 + 2 * (l & 3);
                const float* c = acc[mi][ni];
                float2 v0; v0.x = c[0]; v0.y = c[1];
                float2 v1; v1.x = c[2]; v1.y = c[3];
                *(float2*)(sf + mb * 72 + cc)       = v0;
                *(float2*)(sf + (mb + 8) * 72 + cc) = v1;
            }
        __syncthreads();
        const int h = blockIdx.x;
        const int b = m0 >> 10;
        const int ntok0 = m0 & 1023;
        const int hd = t & 63;
        const int tg = t >> 6;          // 0..3 (32 tokens each)
        const int gbase = (((b * Hh + h) * HDIM) + hd) * Nn + ntok0 + tg * 32;
        #pragma unroll
        for (int grp = 0; grp < 2; grp++) {
            const int tb = tg * 32 + grp * 16;
            #pragma unroll
            for (int j = 0; j < 4; j++) {
                float v0 = sf[(tb + 2*j    ) * 72 + hd];
                float v1 = sf[(tb + 2*j + 1) * 72 + hd];
                float v2 = sf[(tb + 8 + 2*j    ) * 72 + hd];
                float v3 = sf[(tb + 8 + 2*j + 1) * 72 + hd];
                *(unsigned*)&g_vt[gbase + grp * 16 + 4*j    ] = packh2(v0, v1);
                *(unsigned*)&g_vt[gbase + grp * 16 + 4*j + 2] = packh2(v2, v3);
            }
        }
    } else {
        // oproj: y = acc + x + bo  -> g_y (fp32)
        #pragma unroll
        for (int mi = 0; mi < 2; mi++)
            #pragma unroll
            for (int ni = 0; ni < 4; ni++) {
                const int m  = m0 + wm * 32 + mi * 16 + (l >> 2);
                const int gc = n0 + wn * 32 + ni * 8 + 2 * (l & 3);
                const float* c = acc[mi][ni];
                float2 bv = *(const float2*)&bo[gc];
                #pragma unroll
                for (int rr = 0; rr < 2; rr++) {
                    const int mr = m + rr * 8;
                    float2 xv = *(const float2*)&xres[mr * Dd + gc];
                    float2 o;
                    o.x = c[rr * 2 + 0] + xv.x + bv.x;
                    o.y = c[rr * 2 + 1] + xv.y + bv.y;
                    *(float2*)&g_y[mr * Dd + gc] = o;
                }
            }
    }
}

// ---------------- flash attention, fp16 mma, M=32 rows/warp ----------------
// 256 threads, 8 warps x 32 q rows = 256-row Q tile, grid 256. 32-key tiles,
// double-buffered, one barrier/iter. Max-free softmax: p = exp2(s*log2e/8);
// masked -> exp2(-3000) = +0. Score C-frags pack directly into PV k16 A-frags;
// V^T key-permutation makes its uint2 loads match the same logical k.
#define QSU 40                        // Q/K u32 row stride (64 halfs + pad)
#define VSU 24                        // V^T u32 row stride (32 halfs + pad)
#define ASTAGEU (32*QSU + 64*VSU)     // 2816 u32 per stage
#define AQFU (256*QSU)                // 10240 u32
__global__ void __launch_bounds__(256, 2) attn_kernel() {
    extern __shared__ unsigned sma[];
    unsigned* sQ = sma;                       // 256 x 40 u32

    const int qt = blockIdx.x;   // 0..3
    const int h  = blockIdx.y;
    const int b  = blockIdx.z;
    const int bh = b * Hh + h;
    const int t  = threadIdx.x;
    const int l  = t & 31;
    const int w  = t >> 5;                    // 32 q rows per warp
    const int rq = qt * 256 + w * 32 + (l >> 2);

    // Q tile 256x64 halfs -> smem (async, commit group 0)
    #pragma unroll
    for (int it = 0; it < 8; it++) {
        const int u = t + it * 256;
        const int row = u >> 3;
        const int q   = u & 7;
        cp16(&sQ[row * QSU + q * 4], &g_q[((bh * Nn) + qt * 256 + row) * HDIM + q * 8]);
    }

    auto load_stage = [&](int s, int kt) {
        unsigned* sK = sma + AQFU + s * ASTAGEU;
        unsigned* sV = sK + 32 * QSU;
        { // K: 32 rows x 4 chunks = 256 cp16 (threads 0..255, 1 each)
            const int row = t >> 3;
            const int q   = t & 7;
            cp16(&sK[row * QSU + q * 4], &g_k[((bh * Nn) + kt * 32 + row) * HDIM + q * 8]);
        }
        { // V^T: 64 rows x 4 chunks of 16B (32 keys = 64B/row) = 256 cp16
            const int row = t >> 2;
            const int q   = t & 3;
            cp16(&sV[row * VSU + q * 4], &g_vt[((bh * HDIM) + row) * Nn + kt * 32 + q * 8]);
        }
    };

    load_stage(0, 0);
    cp_commit();

    float o[2][8][4];
    #pragma unroll
    for (int mi = 0; mi < 2; mi++)
        #pragma unroll
        for (int nj = 0; nj < 8; nj++)
            #pragma unroll
            for (int c = 0; c < 4; c++) o[mi][nj][c] = 0.f;
    float lp[2][2] = {{0.f, 0.f}, {0.f, 0.f}};

    const float SC = 0.1803368867f;           // log2(e) / 8

    for (int kt = 0; kt < 32; kt++) {
        cp_wait0();
        __syncthreads();
        if (kt < 31) { load_stage((kt + 1) & 1, kt + 1); cp_commit(); }

        const unsigned* sK = sma + AQFU + (kt & 1) * ASTAGEU;
        const unsigned* sV = sK + 32 * QSU;

        // ---- scores S[32 x 32] per warp (2 m16 tiles, 4 n8 tiles) ----
        float s[2][4][4];
        #pragma unroll
        for (int mi = 0; mi < 2; mi++)
            #pragma unroll
            for (int ni = 0; ni < 4; ni++)
                #pragma unroll
                for (int c = 0; c < 4; c++) s[mi][ni][c] = 0.f;

        #pragma unroll
        for (int ks = 0; ks < 4; ks++) {      // 4 k16-slices over hd=64
            const int kc = ks * 8 + 2 * (l & 3);
            unsigned af[2][4];
            #pragma unroll
            for (int mi = 0; mi < 2; mi++) {
                const int rb = w * 32 + mi * 16 + (l >> 2);
                uint2 r0 = *(const uint2*)(sQ + rb * QSU + kc);
                uint2 r8 = *(const uint2*)(sQ + (rb + 8) * QSU + kc);
                af[mi][0] = r0.x; af[mi][1] = r8.x; af[mi][2] = r0.y; af[mi][3] = r8.y;
            }
            #pragma unroll
            for (int ni = 0; ni < 4; ni++) {
                uint2 bv = *(const uint2*)(sK + (ni * 8 + (l >> 2)) * QSU + kc);
                #pragma unroll
                for (int mi = 0; mi < 2; mi++) {
                    float* c = s[mi][ni];
                    mma_f16(c[0], c[1], c[2], c[3],
                            af[mi][0], af[mi][1], af[mi][2], af[mi][3], bv.x, bv.y);
                }
            }
        }

        // ---- mask + scale into log2 domain (masked -> -3000 -> exp2 = +0) ----
        unsigned mw[2][2];
        #pragma unroll
        for (int mi = 0; mi < 2; mi++) {
            mw[mi][0] = g_adjbits[(b * Nn + rq + mi * 16) * (Nn / 32) + kt];
            mw[mi][1] = g_adjbits[(b * Nn + rq + mi * 16 + 8) * (Nn / 32) + kt];
        }
        #pragma unroll
        for (int mi = 0; mi < 2; mi++)
            #pragma unroll
            for (int ni = 0; ni < 4; ni++) {
                const int k0 = ni * 8 + 2 * (l & 3);
                const unsigned b0 = (mw[mi][0] >> k0) & 3u;
                const unsigned b1 = (mw[mi][1] >> k0) & 3u;
                float* c = s[mi][ni];
                c[0] = (b0 & 1u) ? c[0] * SC : -3000.f;
                c[1] = (b0 & 2u) ? c[1] * SC : -3000.f;
                c[2] = (b1 & 1u) ? c[2] * SC : -3000.f;
                c[3] = (b1 & 2u) ? c[3] * SC : -3000.f;
            }

        // ---- P = exp2(s); pack score C-frags into PV k16 A-frags ----
        // group g uses score tiles 2g (logical k 0..7) and 2g+1 (logical k 8..15);
        // V^T key-perm makes b-uint2s carry the matching keys.
        #pragma unroll
        for (int g = 0; g < 2; g++) {
            unsigned pa[2][4];
            #pragma unroll
            for (int mi = 0; mi < 2; mi++) {
                const float pA0 = exp2f(s[mi][2*g][0]);
                const float pA1 = exp2f(s[mi][2*g][1]);
                const float pA2 = exp2f(s[mi][2*g][2]);
                const float pA3 = exp2f(s[mi][2*g][3]);
                const float pB0 = exp2f(s[mi][2*g+1][0]);
                const float pB1 = exp2f(s[mi][2*g+1][1]);
                const float pB2 = exp2f(s[mi][2*g+1][2]);
                const float pB3 = exp2f(s[mi][2*g+1][3]);
                lp[mi][0] += pA0 + pA1 + pB0 + pB1;
                lp[mi][1] += pA2 + pA3 + pB2 + pB3;
                pa[mi][0] = packh2(pA0, pA1);   // rows (l>>2), logical k 2j,2j+1
                pa[mi][1] = packh2(pA2, pA3);   // rows +8
                pa[mi][2] = packh2(pB0, pB1);   // logical k 8+2j,+1
                pa[mi][3] = packh2(pB2, pB3);
            }
            const int kc = g * 8 + 2 * (l & 3);
            #pragma unroll
            for (int nj = 0; nj < 8; nj++) {
                uint2 bv = *(const uint2*)(sV + (nj * 8 + (l >> 2)) * VSU + kc);
                #pragma unroll
                for (int mi = 0; mi < 2; mi++) {
                    float* c = o[mi][nj];
                    mma_f16(c[0], c[1], c[2], c[3],
                            pa[mi][0], pa[mi][1], pa[mi][2], pa[mi][3], bv.x, bv.y);
                }
            }
        }
    }

    // ---- final row-sum reduction + epilogue (ctx fp16, [B,N,D] head-concat) ----
    #pragma unroll
    for (int mi = 0; mi < 2; mi++) {
        float l0 = lp[mi][0], l1 = lp[mi][1];
        l0 += __shfl_xor_sync(0xffffffffu, l0, 1);
        l0 += __shfl_xor_sync(0xffffffffu, l0, 2);
        l1 += __shfl_xor_sync(0xffffffffu, l1, 1);
        l1 += __shfl_xor_sync(0xffffffffu, l1, 2);
        const float inv0 = 1.f / l0;
        const float inv1 = 1.f / l1;
        const int row0g = b * Nn + rq + mi * 16;
        #pragma unroll
        for (int nj = 0; nj < 8; nj++) {
            const int c = h * HDIM + nj * 8 + 2 * (l & 3);
            const float* oc = o[mi][nj];
            *(unsigned*)&g_c[row0g * Dd + c]       = packh2(oc[0] * inv0, oc[1] * inv0);
            *(unsigned*)&g_c[(row0g + 8) * Dd + c] = packh2(oc[2] * inv1, oc[3] * inv1);
        }
    }
}

// ---------------- LayerNorm over D=512 per row ----------------
__global__ void __launch_bounds__(256) ln_kernel(
    const float* __restrict__ gamma,
    const float* __restrict__ beta,
    float* __restrict__ out)
{
    const int row = blockIdx.x;
    const int t   = threadIdx.x;
    const float* __restrict__ y = g_y + row * Dd;

    float2 v = *(const float2*)&y[t * 2];
    float s = v.x + v.y;
    float q = v.x * v.x + v.y * v.y;
    #pragma unroll
    for (int o = 16; o > 0; o >>= 1) {
        s += __shfl_xor_sync(0xffffffffu, s, o);
        q += __shfl_xor_sync(0xffffffffu, q, o);
    }
    __shared__ float ssum[8], ssq[8];
    if ((t & 31) == 0) { ssum[t >> 5] = s; ssq[t >> 5] = q; }
    __syncthreads();
    float ts = 0.f, tq = 0.f;
    #pragma unroll
    for (int wv = 0; wv < 8; wv++) { ts += ssum[wv]; tq += ssq[wv]; }

    const float mean = ts * (1.f / 512.f);
    const float var  = tq * (1.f / 512.f) - mean * mean;
    const float inv  = rsqrtf(var + 1e-5f);

    float2 g  = *(const float2*)&gamma[t * 2];
    float2 bt = *(const float2*)&beta[t * 2];
    float2 o;
    o.x = (v.x - mean) * inv * g.x + bt.x;
    o.y = (v.y - mean) * inv * g.y + bt.y;
    *(float2*)&out[row * Dd + t * 2] = o;
}

// ---------------------------------------------------------------------------
extern "C" void kernel_launch(void* const* d_in, const int* in_sizes, int n_in,
                              void* d_out, int out_size)
{
    const float* x     = (const float*)d_in[0];
    const int*   adj   = (const int*)  d_in[1];
    const float* wq    = (const float*)d_in[2];
    const float* wk    = (const float*)d_in[3];
    const float* wv    = (const float*)d_in[4];
    const float* wo    = (const float*)d_in[5];
    const float* bo    = (const float*)d_in[6];
    const float* gamma = (const float*)d_in[7];
    const float* beta  = (const float*)d_in[8];
    float* out = (float*)d_out;

    const int gemm_smem = 2 * GSTAGEU * 4;                  // 61440 B
    const int attn_smem = (AQFU + 2 * ASTAGEU) * 4;         // 63488 B
    cudaFuncSetAttribute(gemm_f16,   cudaFuncAttributeMaxDynamicSharedMemorySize, gemm_smem);
    cudaFuncSetAttribute(attn_kernel, cudaFuncAttributeMaxDynamicSharedMemorySize, attn_smem);

    prep_kernel<<<6144, 256>>>(x, wq, wk, wv, wo, adj);
    gemm_f16<<<dim3(8, 64, 3), 256, gemm_smem>>>(-1, nullptr, nullptr);
    attn_kernel<<<dim3(4, Hh, Bb), 256, attn_smem>>>();
    gemm_f16<<<dim3(8, 64, 1), 256, gemm_smem>>>(3, x, bo);
    ln_kernel<<<Bb * Nn, 256>>>(gamma, beta, out);
}